// round 1
// baseline (speedup 1.0000x reference)
#include <cuda_runtime.h>

// Problem constants
#define BATCH   2
#define SEQ     2048
#define HID     2048
#define NHEADS  16
#define HDIM    128
#define MROWS   (BATCH*SEQ)      // 4096
#define NQKV    (3*HID)          // 6144

// Scratch (device globals: allocation-free)
__device__ float g_q[(size_t)BATCH*NHEADS*SEQ*HDIM];
__device__ float g_k[(size_t)BATCH*NHEADS*SEQ*HDIM];
__device__ float g_v[(size_t)BATCH*NHEADS*SEQ*HDIM];
__device__ float g_attn[(size_t)BATCH*SEQ*HID];

// ---------------------------------------------------------------------------
// GEMM: out[m,n] = sum_k A[m,k] * W[n,k] + bias[n]   (NT, both K-contiguous)
// MODE 0: A = hidden_states, N=6144, scatter into g_q/g_k/g_v head layout
// MODE 1: A = g_attn,        N=2048, write row-major to d_out
// Tile 128x128x8, 256 threads, 8x8 per-thread micro-tile.
// ---------------------------------------------------------------------------
template<int MODE>
__global__ __launch_bounds__(256, 2)
void gemm_nt_kernel(const float* __restrict__ A,
                    const float* __restrict__ W,
                    const float* __restrict__ bias,
                    float* __restrict__ out)
{
    constexpr int KD = HID;  // 2048
    const float* Aptr = (MODE == 0) ? A : g_attn;

    __shared__ float As[8][128];
    __shared__ float Bs[8][128];

    const int tid  = threadIdx.x;
    const int tx   = tid & 15;
    const int ty   = tid >> 4;
    const int row0 = blockIdx.y * 128;
    const int col0 = blockIdx.x * 128;

    const int lr = tid >> 1;        // 0..127
    const int lk = (tid & 1) * 4;   // 0 or 4

    const float* aG = Aptr + (size_t)(row0 + lr) * KD + lk;
    const float* bG = W    + (size_t)(col0 + lr) * KD + lk;

    float acc[8][8];
#pragma unroll
    for (int i = 0; i < 8; i++)
#pragma unroll
        for (int j = 0; j < 8; j++) acc[i][j] = 0.f;

    for (int k0 = 0; k0 < KD; k0 += 8) {
        float4 a4 = *(const float4*)(aG + k0);
        float4 b4 = *(const float4*)(bG + k0);
        As[lk + 0][lr] = a4.x; As[lk + 1][lr] = a4.y;
        As[lk + 2][lr] = a4.z; As[lk + 3][lr] = a4.w;
        Bs[lk + 0][lr] = b4.x; Bs[lk + 1][lr] = b4.y;
        Bs[lk + 2][lr] = b4.z; Bs[lk + 3][lr] = b4.w;
        __syncthreads();

#pragma unroll
        for (int kk = 0; kk < 8; kk++) {
            float4 a0 = *(const float4*)&As[kk][ty * 8];
            float4 a1 = *(const float4*)&As[kk][ty * 8 + 4];
            float4 b0 = *(const float4*)&Bs[kk][tx * 8];
            float4 b1 = *(const float4*)&Bs[kk][tx * 8 + 4];
            float av[8] = {a0.x, a0.y, a0.z, a0.w, a1.x, a1.y, a1.z, a1.w};
            float bv[8] = {b0.x, b0.y, b0.z, b0.w, b1.x, b1.y, b1.z, b1.w};
#pragma unroll
            for (int i = 0; i < 8; i++)
#pragma unroll
                for (int j = 0; j < 8; j++)
                    acc[i][j] = fmaf(av[i], bv[j], acc[i][j]);
        }
        __syncthreads();
    }

    // Epilogue
    float bb[8];
#pragma unroll
    for (int j = 0; j < 8; j++) bb[j] = bias[col0 + tx * 8 + j];

    if (MODE == 1) {
#pragma unroll
        for (int i = 0; i < 8; i++) {
            int m = row0 + ty * 8 + i;
            float* dst = out + (size_t)m * HID + col0 + tx * 8;
            float4 w0 = {acc[i][0] + bb[0], acc[i][1] + bb[1],
                         acc[i][2] + bb[2], acc[i][3] + bb[3]};
            float4 w1 = {acc[i][4] + bb[4], acc[i][5] + bb[5],
                         acc[i][6] + bb[6], acc[i][7] + bb[7]};
            *(float4*)(dst)     = w0;
            *(float4*)(dst + 4) = w1;
        }
    } else {
        // col0 is a multiple of 128 -> block-uniform target tensor + head
        const int which = col0 >> 11;            // 0=q 1=k 2=v
        const int h     = (col0 & 2047) >> 7;    // head index
        float* base = (which == 0) ? g_q : (which == 1) ? g_k : g_v;
#pragma unroll
        for (int i = 0; i < 8; i++) {
            int m = row0 + ty * 8 + i;
            int b = m >> 11;
            int s = m & 2047;
            float* dst = base + ((size_t)(b * NHEADS + h) * SEQ + s) * HDIM + tx * 8;
            float4 w0 = {acc[i][0] + bb[0], acc[i][1] + bb[1],
                         acc[i][2] + bb[2], acc[i][3] + bb[3]};
            float4 w1 = {acc[i][4] + bb[4], acc[i][5] + bb[5],
                         acc[i][6] + bb[6], acc[i][7] + bb[7]};
            *(float4*)(dst)     = w0;
            *(float4*)(dst + 4) = w1;
        }
    }
}

// ---------------------------------------------------------------------------
// Flash attention (fp32, causal). One block = 64 q-rows of one (b,h).
// 256 threads. S-tile 64x64, online softmax, O accumulated in registers.
// Writes result directly in [B,S,H] layout to g_attn.
// ---------------------------------------------------------------------------
#define FLASH_SMEM_FLOATS (64*128 + 64*129 + 64*128 + 64*65 + 3*64)
#define FLASH_SMEM_BYTES  (FLASH_SMEM_FLOATS * 4)

__global__ void flash_kernel()
{
    // heavy q-tiles first (better tail balance across waves)
    const int qtile = (int)gridDim.x - 1 - (int)blockIdx.x;
    const int bh    = blockIdx.y;
    const float* Q = g_q + (size_t)bh * SEQ * HDIM;
    const float* K = g_k + (size_t)bh * SEQ * HDIM;
    const float* V = g_v + (size_t)bh * SEQ * HDIM;

    extern __shared__ float sm[];
    float* sQ = sm;                    // [64][128]
    float* sK = sQ + 64 * 128;         // [64][129]  (pad: conflict-free-ish col reads)
    float* sV = sK + 64 * 129;         // [64][128]
    float* sP = sV + 64 * 128;         // [64][65]
    float* sM = sP + 64 * 65;          // [64] running max
    float* sL = sM + 64;               // [64] running sum
    float* sA = sL + 64;               // [64] rescale alpha

    const int tid = threadIdx.x;
    const int tx  = tid & 15;
    const int ty  = tid >> 4;

    // Load Q tile
    for (int i = tid; i < 64 * 32; i += 256) {
        int r = i >> 5, c = (i & 31) << 2;
        *(float4*)&sQ[r * 128 + c] =
            *(const float4*)&Q[(size_t)(qtile * 64 + r) * HDIM + c];
    }
    if (tid < 64) { sM[tid] = -1e30f; sL[tid] = 0.f; }

    float o[4][8];
#pragma unroll
    for (int r = 0; r < 4; r++)
#pragma unroll
        for (int c = 0; c < 8; c++) o[r][c] = 0.f;

    const float scale = 0.08838834764831845f;  // 1/sqrt(128)

    for (int kt = 0; kt <= qtile; kt++) {
        __syncthreads();  // previous iter consumers done with sK/sV/sP
        for (int i = tid; i < 64 * 32; i += 256) {
            int r = i >> 5, c = (i & 31) << 2;
            float4 kv = *(const float4*)&K[(size_t)(kt * 64 + r) * HDIM + c];
            sK[r * 129 + c + 0] = kv.x; sK[r * 129 + c + 1] = kv.y;
            sK[r * 129 + c + 2] = kv.z; sK[r * 129 + c + 3] = kv.w;
            *(float4*)&sV[r * 128 + c] =
                *(const float4*)&V[(size_t)(kt * 64 + r) * HDIM + c];
        }
        __syncthreads();

        // S = Q K^T  (4x4 per thread)
        float s4[4][4];
#pragma unroll
        for (int r = 0; r < 4; r++)
#pragma unroll
            for (int c = 0; c < 4; c++) s4[r][c] = 0.f;

#pragma unroll 4
        for (int d = 0; d < 128; d++) {
            float qv[4], kv[4];
#pragma unroll
            for (int r = 0; r < 4; r++) qv[r] = sQ[(ty * 4 + r) * 128 + d];
#pragma unroll
            for (int c = 0; c < 4; c++) kv[c] = sK[(tx * 4 + c) * 129 + d];
#pragma unroll
            for (int r = 0; r < 4; r++)
#pragma unroll
                for (int c = 0; c < 4; c++)
                    s4[r][c] = fmaf(qv[r], kv[c], s4[r][c]);
        }

        const int qi = qtile * 64 + ty * 4;
        const int kj = kt * 64 + tx * 4;
#pragma unroll
        for (int r = 0; r < 4; r++)
#pragma unroll
            for (int c = 0; c < 4; c++) {
                float v = s4[r][c] * scale;
                if (kj + c > qi + r) v = -1e30f;  // only bites on diagonal tile
                sP[(ty * 4 + r) * 65 + tx * 4 + c] = v;
            }
        __syncthreads();

        // Online softmax: one thread per row
        if (tid < 64) {
            float mo = sM[tid];
            float rm = mo;
            for (int j = 0; j < 64; j++) rm = fmaxf(rm, sP[tid * 65 + j]);
            float alpha = __expf(mo - rm);
            float sum = 0.f;
            for (int j = 0; j < 64; j++) {
                float p = __expf(sP[tid * 65 + j] - rm);
                sP[tid * 65 + j] = p;
                sum += p;
            }
            sL[tid] = sL[tid] * alpha + sum;
            sM[tid] = rm;
            sA[tid] = alpha;
        }
        __syncthreads();

        // O = O*alpha + P @ V   (4 rows x 8 d-cols per thread)
#pragma unroll
        for (int r = 0; r < 4; r++) {
            float a = sA[ty * 4 + r];
#pragma unroll
            for (int c = 0; c < 8; c++) o[r][c] *= a;
        }
#pragma unroll 2
        for (int k = 0; k < 64; k++) {
            float p0 = sP[(ty * 4 + 0) * 65 + k];
            float p1 = sP[(ty * 4 + 1) * 65 + k];
            float p2 = sP[(ty * 4 + 2) * 65 + k];
            float p3 = sP[(ty * 4 + 3) * 65 + k];
            float4 v0 = *(const float4*)&sV[k * 128 + tx * 8];
            float4 v1 = *(const float4*)&sV[k * 128 + tx * 8 + 4];
            o[0][0] = fmaf(p0, v0.x, o[0][0]); o[0][1] = fmaf(p0, v0.y, o[0][1]);
            o[0][2] = fmaf(p0, v0.z, o[0][2]); o[0][3] = fmaf(p0, v0.w, o[0][3]);
            o[0][4] = fmaf(p0, v1.x, o[0][4]); o[0][5] = fmaf(p0, v1.y, o[0][5]);
            o[0][6] = fmaf(p0, v1.z, o[0][6]); o[0][7] = fmaf(p0, v1.w, o[0][7]);
            o[1][0] = fmaf(p1, v0.x, o[1][0]); o[1][1] = fmaf(p1, v0.y, o[1][1]);
            o[1][2] = fmaf(p1, v0.z, o[1][2]); o[1][3] = fmaf(p1, v0.w, o[1][3]);
            o[1][4] = fmaf(p1, v1.x, o[1][4]); o[1][5] = fmaf(p1, v1.y, o[1][5]);
            o[1][6] = fmaf(p1, v1.z, o[1][6]); o[1][7] = fmaf(p1, v1.w, o[1][7]);
            o[2][0] = fmaf(p2, v0.x, o[2][0]); o[2][1] = fmaf(p2, v0.y, o[2][1]);
            o[2][2] = fmaf(p2, v0.z, o[2][2]); o[2][3] = fmaf(p2, v0.w, o[2][3]);
            o[2][4] = fmaf(p2, v1.x, o[2][4]); o[2][5] = fmaf(p2, v1.y, o[2][5]);
            o[2][6] = fmaf(p2, v1.z, o[2][6]); o[2][7] = fmaf(p2, v1.w, o[2][7]);
            o[3][0] = fmaf(p3, v0.x, o[3][0]); o[3][1] = fmaf(p3, v0.y, o[3][1]);
            o[3][2] = fmaf(p3, v0.z, o[3][2]); o[3][3] = fmaf(p3, v0.w, o[3][3]);
            o[3][4] = fmaf(p3, v1.x, o[3][4]); o[3][5] = fmaf(p3, v1.y, o[3][5]);
            o[3][6] = fmaf(p3, v1.z, o[3][6]); o[3][7] = fmaf(p3, v1.w, o[3][7]);
        }
    }

    // Normalize + write to [B,S,H] layout
    const int b = bh >> 4, h = bh & 15;
#pragma unroll
    for (int r = 0; r < 4; r++) {
        int i = ty * 4 + r;
        float inv = 1.f / sL[i];
        int sg = qtile * 64 + i;
        float* dst = g_attn + ((size_t)(b * SEQ + sg)) * HID + h * HDIM + tx * 8;
        float4 w0 = {o[r][0] * inv, o[r][1] * inv, o[r][2] * inv, o[r][3] * inv};
        float4 w1 = {o[r][4] * inv, o[r][5] * inv, o[r][6] * inv, o[r][7] * inv};
        *(float4*)(dst)     = w0;
        *(float4*)(dst + 4) = w1;
    }
}

// ---------------------------------------------------------------------------
extern "C" void kernel_launch(void* const* d_in, const int* in_sizes, int n_in,
                              void* d_out, int out_size)
{
    const float* hs    = (const float*)d_in[0];
    const float* W_in  = (const float*)d_in[1];
    const float* b_in  = (const float*)d_in[2];
    const float* W_out = (const float*)d_in[3];
    const float* b_out = (const float*)d_in[4];
    float* out = (float*)d_out;
    (void)in_sizes; (void)n_in; (void)out_size;

    cudaFuncSetAttribute(flash_kernel,
                         cudaFuncAttributeMaxDynamicSharedMemorySize,
                         FLASH_SMEM_BYTES);

    // 1) QKV projection, scatter to head layout
    gemm_nt_kernel<0><<<dim3(NQKV / 128, MROWS / 128), 256>>>(hs, W_in, b_in, nullptr);
    // 2) causal flash attention, writes [B,S,H]
    flash_kernel<<<dim3(SEQ / 64, BATCH * NHEADS), 256, FLASH_SMEM_BYTES>>>();
    // 3) output projection -> d_out
    gemm_nt_kernel<1><<<dim3(HID / 128, MROWS / 128), 256>>>(nullptr, W_out, b_out, out);
}

// round 3
// speedup vs baseline: 1.1707x; 1.1707x over previous
#include <cuda_runtime.h>
#include <cuda_bf16.h>
#include <cstdint>

// Problem constants
#define BATCH   2
#define SEQ     2048
#define HID     2048
#define NHEADS  16
#define HDIM    128
#define MROWS   (BATCH*SEQ)      // 4096
#define NQKV    (3*HID)          // 6144

// Scratch (device globals: allocation-free)
__device__ float g_q[(size_t)BATCH*NHEADS*SEQ*HDIM];
__device__ float g_k[(size_t)BATCH*NHEADS*SEQ*HDIM];
__device__ float g_v[(size_t)BATCH*NHEADS*SEQ*HDIM];
__device__ float g_attn[(size_t)BATCH*SEQ*HID];

// bf16 hi/lo decompositions
__device__ __nv_bfloat16 g_hs_hi[(size_t)MROWS*HID],   g_hs_lo[(size_t)MROWS*HID];
__device__ __nv_bfloat16 g_win_hi[(size_t)NQKV*HID],   g_win_lo[(size_t)NQKV*HID];
__device__ __nv_bfloat16 g_wout_hi[(size_t)HID*HID],   g_wout_lo[(size_t)HID*HID];
__device__ __nv_bfloat16 g_attn_hi[(size_t)MROWS*HID], g_attn_lo[(size_t)MROWS*HID];

__device__ __forceinline__ uint32_t smem_to_u32(const void* p) {
    uint32_t a;
    asm("{ .reg .u64 t; cvta.to.shared.u64 t, %1; cvt.u32.u64 %0, t; }"
        : "=r"(a) : "l"(p));
    return a;
}

// ---------------------------------------------------------------------------
// fp32 -> bf16 hi/lo conversion (grid-stride, vectorized)
// ---------------------------------------------------------------------------
__global__ void cvt_hilo_kernel(const float* __restrict__ src,
                                __nv_bfloat16* __restrict__ hi,
                                __nv_bfloat16* __restrict__ lo,
                                int n4)
{
    for (int i = blockIdx.x * blockDim.x + threadIdx.x; i < n4;
         i += gridDim.x * blockDim.x) {
        float4 v = ((const float4*)src)[i];
        __nv_bfloat162 h0 = __float22bfloat162_rn(make_float2(v.x, v.y));
        __nv_bfloat162 h1 = __float22bfloat162_rn(make_float2(v.z, v.w));
        float2 f0 = __bfloat1622float2(h0);
        float2 f1 = __bfloat1622float2(h1);
        __nv_bfloat162 l0 = __float22bfloat162_rn(make_float2(v.x - f0.x, v.y - f0.y));
        __nv_bfloat162 l1 = __float22bfloat162_rn(make_float2(v.z - f1.x, v.w - f1.y));
        uint2 hp, lp;
        hp.x = *(uint32_t*)&h0; hp.y = *(uint32_t*)&h1;
        lp.x = *(uint32_t*)&l0; lp.y = *(uint32_t*)&l1;
        ((uint2*)hi)[i] = hp;
        ((uint2*)lo)[i] = lp;
    }
}

// ---------------------------------------------------------------------------
// HMMA GEMM (bf16x3): out[m,n] = sum_k A[m,k]*W[n,k] + bias[n]
// Block 128x128, 8 warps (each 32x64), K-chunk 64, cp.async double buffer.
// MODE 0: scatter to g_q/g_k/g_v head layout;  MODE 1: row-major to out.
// ---------------------------------------------------------------------------
#define ROWB 144                 // smem row stride bytes (72 bf16) -> conflict-free ldmatrix
#define TILE_B (128*ROWB)        // 18432
#define AT_HI 0
#define AT_LO TILE_B
#define BT_HI (2*TILE_B)
#define BT_LO (3*TILE_B)
#define STAGE_B (4*TILE_B)       // 73728
#define GEMM_SMEM (2*STAGE_B)    // 147456

__device__ __forceinline__ void ldsm_x4(uint32_t* r, uint32_t addr) {
    asm volatile("ldmatrix.sync.aligned.m8n8.x4.shared.b16 {%0,%1,%2,%3}, [%4];"
                 : "=r"(r[0]), "=r"(r[1]), "=r"(r[2]), "=r"(r[3]) : "r"(addr));
}
__device__ __forceinline__ void mma_bf16(float* d, const uint32_t* a,
                                         uint32_t b0, uint32_t b1) {
    asm volatile("mma.sync.aligned.m16n8k16.row.col.f32.bf16.bf16.f32 "
                 "{%0,%1,%2,%3}, {%4,%5,%6,%7}, {%8,%9}, {%0,%1,%2,%3};"
                 : "+f"(d[0]), "+f"(d[1]), "+f"(d[2]), "+f"(d[3])
                 : "r"(a[0]), "r"(a[1]), "r"(a[2]), "r"(a[3]), "r"(b0), "r"(b1));
}
__device__ __forceinline__ void cp_async16(uint32_t dst, const void* src) {
    asm volatile("cp.async.cg.shared.global [%0], [%1], 16;" :: "r"(dst), "l"(src));
}

template<int MODE, int KDIM>
__global__ __launch_bounds__(256, 1)
void gemm_mma_kernel(const __nv_bfloat16* __restrict__ Ah,
                     const __nv_bfloat16* __restrict__ Al,
                     const __nv_bfloat16* __restrict__ Bh,
                     const __nv_bfloat16* __restrict__ Bl,
                     const float* __restrict__ bias,
                     float* __restrict__ out)
{
    extern __shared__ char smem[];
    const uint32_t smb = smem_to_u32(smem);
    const int tid  = threadIdx.x;
    const int wid  = tid >> 5;
    const int lane = tid & 31;
    const int warp_m = wid & 3;      // 4 warps over M (32 rows each)
    const int warp_n = wid >> 2;     // 2 warps over N (64 cols each)
    const int row0 = blockIdx.y * 128;
    const int col0 = blockIdx.x * 128;
    constexpr int NCHUNK = KDIM / 64;

    // cp.async tile sources (rows of 64 bf16 = 8 x 16B per row)
    const __nv_bfloat16* srcs[4] = {
        Ah + (size_t)row0 * KDIM, Al + (size_t)row0 * KDIM,
        Bh + (size_t)col0 * KDIM, Bl + (size_t)col0 * KDIM };

    auto issue = [&](int c, int st) {
        const int k0 = c * 64;
        const uint32_t sb = smb + st * STAGE_B;
#pragma unroll
        for (int t = 0; t < 4; ++t) {
            const __nv_bfloat16* s = srcs[t];
            const uint32_t db = sb + t * TILE_B;
#pragma unroll
            for (int i = 0; i < 4; ++i) {
                int idx = i * 256 + tid;          // 0..1023
                int row = idx >> 3, ch = idx & 7;
                cp_async16(db + row * ROWB + ch * 16,
                           s + (size_t)row * KDIM + k0 + ch * 8);
            }
        }
    };

    float acc[2][8][4];
#pragma unroll
    for (int i = 0; i < 2; i++)
#pragma unroll
        for (int j = 0; j < 8; j++)
#pragma unroll
            for (int q = 0; q < 4; q++) acc[i][j][q] = 0.f;

    // ldmatrix per-lane address components
    const int rowA = (lane & 7) + ((lane >> 3) & 1) * 8;
    const int kA   = (lane >> 4) * 8;
    const int rowB = (lane & 7) + (lane >> 4) * 8;
    const int kB   = ((lane >> 3) & 1) * 8;

    issue(0, 0);
    asm volatile("cp.async.commit_group;");

    for (int c = 0; c < NCHUNK; ++c) {
        __syncthreads();                      // buffer (c+1)&1 free to overwrite
        if (c + 1 < NCHUNK) issue(c + 1, (c + 1) & 1);
        asm volatile("cp.async.commit_group;");
        asm volatile("cp.async.wait_group 1;");
        __syncthreads();

        const uint32_t sb = smb + (c & 1) * STAGE_B;
        uint32_t aBase[2], bBase[4];
#pragma unroll
        for (int mf = 0; mf < 2; ++mf)
            aBase[mf] = sb + (warp_m * 32 + mf * 16 + rowA) * ROWB + kA * 2;
#pragma unroll
        for (int nf = 0; nf < 4; ++nf)
            bBase[nf] = sb + BT_HI + (warp_n * 64 + nf * 16 + rowB) * ROWB + kB * 2;

#pragma unroll
        for (int ks = 0; ks < 4; ++ks) {
            const int kb2 = ks * 32;          // 16 elems * 2B
            uint32_t a_hi[2][4], a_lo[2][4];
#pragma unroll
            for (int mf = 0; mf < 2; ++mf) {
                ldsm_x4(a_hi[mf], aBase[mf] + AT_HI + kb2);
                ldsm_x4(a_lo[mf], aBase[mf] + AT_LO + kb2);
            }
            uint32_t b_hi[4][4], b_lo[4][4];
#pragma unroll
            for (int nf = 0; nf < 4; ++nf) {
                ldsm_x4(b_hi[nf], bBase[nf] + kb2);
                ldsm_x4(b_lo[nf], bBase[nf] + TILE_B + kb2);
            }
#pragma unroll
            for (int mf = 0; mf < 2; ++mf)
#pragma unroll
                for (int nf = 0; nf < 8; ++nf) {
                    const uint32_t* bh = &b_hi[nf >> 1][(nf & 1) * 2];
                    const uint32_t* bl = &b_lo[nf >> 1][(nf & 1) * 2];
                    mma_bf16(acc[mf][nf], a_hi[mf], bh[0], bh[1]);
                    mma_bf16(acc[mf][nf], a_hi[mf], bl[0], bl[1]);
                    mma_bf16(acc[mf][nf], a_lo[mf], bh[0], bh[1]);
                }
        }
    }

    // Epilogue
#pragma unroll
    for (int mf = 0; mf < 2; ++mf) {
        const int rbase = row0 + warp_m * 32 + mf * 16 + (lane >> 2);
#pragma unroll
        for (int nf = 0; nf < 8; ++nf) {
            const int col = col0 + warp_n * 64 + nf * 8 + (lane & 3) * 2;
            float2 bv = *(const float2*)&bias[col];
#pragma unroll
            for (int half = 0; half < 2; ++half) {
                const int m = rbase + half * 8;
                float2 w = { acc[mf][nf][half * 2 + 0] + bv.x,
                             acc[mf][nf][half * 2 + 1] + bv.y };
                if (MODE == 1) {
                    *(float2*)(out + (size_t)m * HID + col) = w;
                } else {
                    const int which = col0 >> 11;
                    const int h = (col0 & 2047) >> 7;
                    const int d = col & 127;
                    float* base = (which == 0) ? g_q : (which == 1) ? g_k : g_v;
                    const int b = m >> 11, sI = m & 2047;
                    *(float2*)(base + ((size_t)(b * NHEADS + h) * SEQ + sI) * HDIM + d) = w;
                }
            }
        }
    }
}

// ---------------------------------------------------------------------------
// Flash attention (fp32, causal) — unchanged from R1.
// ---------------------------------------------------------------------------
#define FLASH_SMEM_FLOATS (64*128 + 64*129 + 64*128 + 64*65 + 3*64)
#define FLASH_SMEM_BYTES  (FLASH_SMEM_FLOATS * 4)

__global__ void flash_kernel()
{
    const int qtile = (int)gridDim.x - 1 - (int)blockIdx.x;
    const int bh    = blockIdx.y;
    const float* Q = g_q + (size_t)bh * SEQ * HDIM;
    const float* K = g_k + (size_t)bh * SEQ * HDIM;
    const float* V = g_v + (size_t)bh * SEQ * HDIM;

    extern __shared__ float sm[];
    float* sQ = sm;
    float* sK = sQ + 64 * 128;
    float* sV = sK + 64 * 129;
    float* sP = sV + 64 * 128;
    float* sM = sP + 64 * 65;
    float* sL = sM + 64;
    float* sA = sL + 64;

    const int tid = threadIdx.x;
    const int tx  = tid & 15;
    const int ty  = tid >> 4;

    for (int i = tid; i < 64 * 32; i += 256) {
        int r = i >> 5, c = (i & 31) << 2;
        *(float4*)&sQ[r * 128 + c] =
            *(const float4*)&Q[(size_t)(qtile * 64 + r) * HDIM + c];
    }
    if (tid < 64) { sM[tid] = -1e30f; sL[tid] = 0.f; }

    float o[4][8];
#pragma unroll
    for (int r = 0; r < 4; r++)
#pragma unroll
        for (int c = 0; c < 8; c++) o[r][c] = 0.f;

    const float scale = 0.08838834764831845f;

    for (int kt = 0; kt <= qtile; kt++) {
        __syncthreads();
        for (int i = tid; i < 64 * 32; i += 256) {
            int r = i >> 5, c = (i & 31) << 2;
            float4 kv = *(const float4*)&K[(size_t)(kt * 64 + r) * HDIM + c];
            sK[r * 129 + c + 0] = kv.x; sK[r * 129 + c + 1] = kv.y;
            sK[r * 129 + c + 2] = kv.z; sK[r * 129 + c + 3] = kv.w;
            *(float4*)&sV[r * 128 + c] =
                *(const float4*)&V[(size_t)(kt * 64 + r) * HDIM + c];
        }
        __syncthreads();

        float s4[4][4];
#pragma unroll
        for (int r = 0; r < 4; r++)
#pragma unroll
            for (int c = 0; c < 4; c++) s4[r][c] = 0.f;

#pragma unroll 4
        for (int d = 0; d < 128; d++) {
            float qv[4], kv[4];
#pragma unroll
            for (int r = 0; r < 4; r++) qv[r] = sQ[(ty * 4 + r) * 128 + d];
#pragma unroll
            for (int c = 0; c < 4; c++) kv[c] = sK[(tx * 4 + c) * 129 + d];
#pragma unroll
            for (int r = 0; r < 4; r++)
#pragma unroll
                for (int c = 0; c < 4; c++)
                    s4[r][c] = fmaf(qv[r], kv[c], s4[r][c]);
        }

        const int qi = qtile * 64 + ty * 4;
        const int kj = kt * 64 + tx * 4;
#pragma unroll
        for (int r = 0; r < 4; r++)
#pragma unroll
            for (int c = 0; c < 4; c++) {
                float v = s4[r][c] * scale;
                if (kj + c > qi + r) v = -1e30f;
                sP[(ty * 4 + r) * 65 + tx * 4 + c] = v;
            }
        __syncthreads();

        if (tid < 64) {
            float mo = sM[tid];
            float rm = mo;
            for (int j = 0; j < 64; j++) rm = fmaxf(rm, sP[tid * 65 + j]);
            float alpha = __expf(mo - rm);
            float sum = 0.f;
            for (int j = 0; j < 64; j++) {
                float p = __expf(sP[tid * 65 + j] - rm);
                sP[tid * 65 + j] = p;
                sum += p;
            }
            sL[tid] = sL[tid] * alpha + sum;
            sM[tid] = rm;
            sA[tid] = alpha;
        }
        __syncthreads();

#pragma unroll
        for (int r = 0; r < 4; r++) {
            float a = sA[ty * 4 + r];
#pragma unroll
            for (int c = 0; c < 8; c++) o[r][c] *= a;
        }
#pragma unroll 2
        for (int k = 0; k < 64; k++) {
            float p0 = sP[(ty * 4 + 0) * 65 + k];
            float p1 = sP[(ty * 4 + 1) * 65 + k];
            float p2 = sP[(ty * 4 + 2) * 65 + k];
            float p3 = sP[(ty * 4 + 3) * 65 + k];
            float4 v0 = *(const float4*)&sV[k * 128 + tx * 8];
            float4 v1 = *(const float4*)&sV[k * 128 + tx * 8 + 4];
            o[0][0] = fmaf(p0, v0.x, o[0][0]); o[0][1] = fmaf(p0, v0.y, o[0][1]);
            o[0][2] = fmaf(p0, v0.z, o[0][2]); o[0][3] = fmaf(p0, v0.w, o[0][3]);
            o[0][4] = fmaf(p0, v1.x, o[0][4]); o[0][5] = fmaf(p0, v1.y, o[0][5]);
            o[0][6] = fmaf(p0, v1.z, o[0][6]); o[0][7] = fmaf(p0, v1.w, o[0][7]);
            o[1][0] = fmaf(p1, v0.x, o[1][0]); o[1][1] = fmaf(p1, v0.y, o[1][1]);
            o[1][2] = fmaf(p1, v0.z, o[1][2]); o[1][3] = fmaf(p1, v0.w, o[1][3]);
            o[1][4] = fmaf(p1, v1.x, o[1][4]); o[1][5] = fmaf(p1, v1.y, o[1][5]);
            o[1][6] = fmaf(p1, v1.z, o[1][6]); o[1][7] = fmaf(p1, v1.w, o[1][7]);
            o[2][0] = fmaf(p2, v0.x, o[2][0]); o[2][1] = fmaf(p2, v0.y, o[2][1]);
            o[2][2] = fmaf(p2, v0.z, o[2][2]); o[2][3] = fmaf(p2, v0.w, o[2][3]);
            o[2][4] = fmaf(p2, v1.x, o[2][4]); o[2][5] = fmaf(p2, v1.y, o[2][5]);
            o[2][6] = fmaf(p2, v1.z, o[2][6]); o[2][7] = fmaf(p2, v1.w, o[2][7]);
            o[3][0] = fmaf(p3, v0.x, o[3][0]); o[3][1] = fmaf(p3, v0.y, o[3][1]);
            o[3][2] = fmaf(p3, v0.z, o[3][2]); o[3][3] = fmaf(p3, v0.w, o[3][3]);
            o[3][4] = fmaf(p3, v1.x, o[3][4]); o[3][5] = fmaf(p3, v1.y, o[3][5]);
            o[3][6] = fmaf(p3, v1.z, o[3][6]); o[3][7] = fmaf(p3, v1.w, o[3][7]);
        }
    }

    const int b = bh >> 4, h = bh & 15;
#pragma unroll
    for (int r = 0; r < 4; r++) {
        int i = ty * 4 + r;
        float inv = 1.f / sL[i];
        int sg = qtile * 64 + i;
        float* dst = g_attn + ((size_t)(b * SEQ + sg)) * HID + h * HDIM + tx * 8;
        float4 w0 = {o[r][0] * inv, o[r][1] * inv, o[r][2] * inv, o[r][3] * inv};
        float4 w1 = {o[r][4] * inv, o[r][5] * inv, o[r][6] * inv, o[r][7] * inv};
        *(float4*)(dst)     = w0;
        *(float4*)(dst + 4) = w1;
    }
}

// ---------------------------------------------------------------------------
extern "C" void kernel_launch(void* const* d_in, const int* in_sizes, int n_in,
                              void* d_out, int out_size)
{
    const float* hs    = (const float*)d_in[0];
    const float* W_in  = (const float*)d_in[1];
    const float* b_in  = (const float*)d_in[2];
    const float* W_out = (const float*)d_in[3];
    const float* b_out = (const float*)d_in[4];
    float* out = (float*)d_out;
    (void)in_sizes; (void)n_in; (void)out_size;

    cudaFuncSetAttribute(gemm_mma_kernel<0, HID>,
                         cudaFuncAttributeMaxDynamicSharedMemorySize, GEMM_SMEM);
    cudaFuncSetAttribute(gemm_mma_kernel<1, HID>,
                         cudaFuncAttributeMaxDynamicSharedMemorySize, GEMM_SMEM);
    cudaFuncSetAttribute(flash_kernel,
                         cudaFuncAttributeMaxDynamicSharedMemorySize, FLASH_SMEM_BYTES);

    // resolve device-global addresses (host-side, not captured)
    __nv_bfloat16 *hs_hi, *hs_lo, *win_hi, *win_lo, *wout_hi, *wout_lo, *at_hi, *at_lo;
    float* attn_f;
    cudaGetSymbolAddress((void**)&hs_hi,  g_hs_hi);
    cudaGetSymbolAddress((void**)&hs_lo,  g_hs_lo);
    cudaGetSymbolAddress((void**)&win_hi, g_win_hi);
    cudaGetSymbolAddress((void**)&win_lo, g_win_lo);
    cudaGetSymbolAddress((void**)&wout_hi, g_wout_hi);
    cudaGetSymbolAddress((void**)&wout_lo, g_wout_lo);
    cudaGetSymbolAddress((void**)&at_hi,  g_attn_hi);
    cudaGetSymbolAddress((void**)&at_lo,  g_attn_lo);
    cudaGetSymbolAddress((void**)&attn_f, g_attn);

    // 0) fp32 -> bf16 hi/lo decompositions
    cvt_hilo_kernel<<<2048, 256>>>(hs,    hs_hi,  hs_lo,  MROWS * HID / 4);
    cvt_hilo_kernel<<<2048, 256>>>(W_in,  win_hi, win_lo, NQKV * HID / 4);
    cvt_hilo_kernel<<<2048, 256>>>(W_out, wout_hi, wout_lo, HID * HID / 4);

    // 1) QKV projection (HMMA bf16x3), scatter to head layout
    gemm_mma_kernel<0, HID><<<dim3(NQKV / 128, MROWS / 128), 256, GEMM_SMEM>>>(
        hs_hi, hs_lo, win_hi, win_lo, b_in, nullptr);

    // 2) causal flash attention -> g_attn [B,S,H]
    flash_kernel<<<dim3(SEQ / 64, BATCH * NHEADS), 256, FLASH_SMEM_BYTES>>>();

    // 3) convert attention output, then output projection -> d_out
    cvt_hilo_kernel<<<2048, 256>>>(attn_f, at_hi, at_lo, MROWS * HID / 4);
    gemm_mma_kernel<1, HID><<<dim3(HID / 128, MROWS / 128), 256, GEMM_SMEM>>>(
        at_hi, at_lo, wout_hi, wout_lo, b_out, out);
}

// round 4
// speedup vs baseline: 1.8396x; 1.5713x over previous
#include <cuda_runtime.h>
#include <cuda_bf16.h>
#include <cstdint>

// Problem constants
#define BATCH   2
#define SEQ     2048
#define HID     2048
#define NHEADS  16
#define HDIM    128
#define MROWS   (BATCH*SEQ)      // 4096
#define NQKV    (3*HID)          // 6144

// Scratch (device globals: allocation-free)
__device__ float g_q[(size_t)BATCH*NHEADS*SEQ*HDIM];
__device__ float g_k[(size_t)BATCH*NHEADS*SEQ*HDIM];
__device__ float g_v[(size_t)BATCH*NHEADS*SEQ*HDIM];

// bf16 hi/lo decompositions
__device__ __nv_bfloat16 g_hs_hi[(size_t)MROWS*HID],   g_hs_lo[(size_t)MROWS*HID];
__device__ __nv_bfloat16 g_win_hi[(size_t)NQKV*HID],   g_win_lo[(size_t)NQKV*HID];
__device__ __nv_bfloat16 g_wout_hi[(size_t)HID*HID],   g_wout_lo[(size_t)HID*HID];
__device__ __nv_bfloat16 g_attn_hi[(size_t)MROWS*HID], g_attn_lo[(size_t)MROWS*HID];

__device__ __forceinline__ uint32_t smem_to_u32(const void* p) {
    uint32_t a;
    asm("{ .reg .u64 t; cvta.to.shared.u64 t, %1; cvt.u32.u64 %0, t; }"
        : "=r"(a) : "l"(p));
    return a;
}

// ---------------------------------------------------------------------------
// fp32 -> bf16 hi/lo conversion (grid-stride, vectorized)
// ---------------------------------------------------------------------------
__global__ void cvt_hilo_kernel(const float* __restrict__ src,
                                __nv_bfloat16* __restrict__ hi,
                                __nv_bfloat16* __restrict__ lo,
                                int n4)
{
    for (int i = blockIdx.x * blockDim.x + threadIdx.x; i < n4;
         i += gridDim.x * blockDim.x) {
        float4 v = ((const float4*)src)[i];
        __nv_bfloat162 h0 = __float22bfloat162_rn(make_float2(v.x, v.y));
        __nv_bfloat162 h1 = __float22bfloat162_rn(make_float2(v.z, v.w));
        float2 f0 = __bfloat1622float2(h0);
        float2 f1 = __bfloat1622float2(h1);
        __nv_bfloat162 l0 = __float22bfloat162_rn(make_float2(v.x - f0.x, v.y - f0.y));
        __nv_bfloat162 l1 = __float22bfloat162_rn(make_float2(v.z - f1.x, v.w - f1.y));
        uint2 hp, lp;
        hp.x = *(uint32_t*)&h0; hp.y = *(uint32_t*)&h1;
        lp.x = *(uint32_t*)&l0; lp.y = *(uint32_t*)&l1;
        ((uint2*)hi)[i] = hp;
        ((uint2*)lo)[i] = lp;
    }
}

// ---------------------------------------------------------------------------
// HMMA GEMM (bf16x3): out[m,n] = sum_k A[m,k]*W[n,k] + bias[n]
// Block 128x128, 8 warps (each 32x64), K-chunk 64, cp.async double buffer.
// Inner loop: compensation passes OUTERMOST -> 16 independent accumulators
// between reuses (no dependent HMMA chains).
// MODE 0: scatter to g_q/g_k/g_v head layout;  MODE 1: row-major to out.
// ---------------------------------------------------------------------------
#define ROWB 144                 // smem row stride bytes -> conflict-free ldmatrix
#define TILE_B (128*ROWB)        // 18432
#define AT_HI 0
#define AT_LO TILE_B
#define BT_HI (2*TILE_B)
#define BT_LO (3*TILE_B)
#define STAGE_B (4*TILE_B)       // 73728
#define GEMM_SMEM (2*STAGE_B)    // 147456

__device__ __forceinline__ void ldsm_x4(uint32_t* r, uint32_t addr) {
    asm volatile("ldmatrix.sync.aligned.m8n8.x4.shared.b16 {%0,%1,%2,%3}, [%4];"
                 : "=r"(r[0]), "=r"(r[1]), "=r"(r[2]), "=r"(r[3]) : "r"(addr));
}
__device__ __forceinline__ void mma_bf16(float* d, const uint32_t* a,
                                         uint32_t b0, uint32_t b1) {
    asm volatile("mma.sync.aligned.m16n8k16.row.col.f32.bf16.bf16.f32 "
                 "{%0,%1,%2,%3}, {%4,%5,%6,%7}, {%8,%9}, {%0,%1,%2,%3};"
                 : "+f"(d[0]), "+f"(d[1]), "+f"(d[2]), "+f"(d[3])
                 : "r"(a[0]), "r"(a[1]), "r"(a[2]), "r"(a[3]), "r"(b0), "r"(b1));
}
__device__ __forceinline__ void cp_async16(uint32_t dst, const void* src) {
    asm volatile("cp.async.cg.shared.global [%0], [%1], 16;" :: "r"(dst), "l"(src));
}

template<int MODE, int KDIM>
__global__ __launch_bounds__(256, 1)
void gemm_mma_kernel(const __nv_bfloat16* __restrict__ Ah,
                     const __nv_bfloat16* __restrict__ Al,
                     const __nv_bfloat16* __restrict__ Bh,
                     const __nv_bfloat16* __restrict__ Bl,
                     const float* __restrict__ bias,
                     float* __restrict__ out)
{
    extern __shared__ char smem[];
    const uint32_t smb = smem_to_u32(smem);
    const int tid  = threadIdx.x;
    const int wid  = tid >> 5;
    const int lane = tid & 31;
    const int warp_m = wid & 3;      // 4 warps over M (32 rows each)
    const int warp_n = wid >> 2;     // 2 warps over N (64 cols each)
    const int row0 = blockIdx.y * 128;
    const int col0 = blockIdx.x * 128;
    constexpr int NCHUNK = KDIM / 64;

    const __nv_bfloat16* srcs[4] = {
        Ah + (size_t)row0 * KDIM, Al + (size_t)row0 * KDIM,
        Bh + (size_t)col0 * KDIM, Bl + (size_t)col0 * KDIM };

    auto issue = [&](int c, int st) {
        const int k0 = c * 64;
        const uint32_t sb = smb + st * STAGE_B;
#pragma unroll
        for (int t = 0; t < 4; ++t) {
            const __nv_bfloat16* s = srcs[t];
            const uint32_t db = sb + t * TILE_B;
#pragma unroll
            for (int i = 0; i < 4; ++i) {
                int idx = i * 256 + tid;
                int row = idx >> 3, ch = idx & 7;
                cp_async16(db + row * ROWB + ch * 16,
                           s + (size_t)row * KDIM + k0 + ch * 8);
            }
        }
    };

    float acc[2][8][4];
#pragma unroll
    for (int i = 0; i < 2; i++)
#pragma unroll
        for (int j = 0; j < 8; j++)
#pragma unroll
            for (int q = 0; q < 4; q++) acc[i][j][q] = 0.f;

    const int rowA = (lane & 7) + ((lane >> 3) & 1) * 8;
    const int kA   = (lane >> 4) * 8;
    const int rowB = (lane & 7) + (lane >> 4) * 8;
    const int kB   = ((lane >> 3) & 1) * 8;

    issue(0, 0);
    asm volatile("cp.async.commit_group;");

    for (int c = 0; c < NCHUNK; ++c) {
        __syncthreads();
        if (c + 1 < NCHUNK) issue(c + 1, (c + 1) & 1);
        asm volatile("cp.async.commit_group;");
        asm volatile("cp.async.wait_group 1;");
        __syncthreads();

        const uint32_t sb = smb + (c & 1) * STAGE_B;
        uint32_t aBase[2], bBase[4];
#pragma unroll
        for (int mf = 0; mf < 2; ++mf)
            aBase[mf] = sb + (warp_m * 32 + mf * 16 + rowA) * ROWB + kA * 2;
#pragma unroll
        for (int nf = 0; nf < 4; ++nf)
            bBase[nf] = sb + BT_HI + (warp_n * 64 + nf * 16 + rowB) * ROWB + kB * 2;

#pragma unroll
        for (int ks = 0; ks < 4; ++ks) {
            const int kb2 = ks * 32;
            uint32_t a_hi[2][4], a_lo[2][4];
#pragma unroll
            for (int mf = 0; mf < 2; ++mf) {
                ldsm_x4(a_hi[mf], aBase[mf] + AT_HI + kb2);
                ldsm_x4(a_lo[mf], aBase[mf] + AT_LO + kb2);
            }
            uint32_t b_hi[4][4], b_lo[4][4];
#pragma unroll
            for (int nf = 0; nf < 4; ++nf) {
                ldsm_x4(b_hi[nf], bBase[nf] + kb2);
                ldsm_x4(b_lo[nf], bBase[nf] + TILE_B + kb2);
            }
            // Pass 1: Ahi*Bhi  (16 independent accumulators in flight)
#pragma unroll
            for (int mf = 0; mf < 2; ++mf)
#pragma unroll
                for (int nf = 0; nf < 8; ++nf) {
                    const uint32_t* bh = &b_hi[nf >> 1][(nf & 1) * 2];
                    mma_bf16(acc[mf][nf], a_hi[mf], bh[0], bh[1]);
                }
            // Pass 2: Ahi*Blo
#pragma unroll
            for (int mf = 0; mf < 2; ++mf)
#pragma unroll
                for (int nf = 0; nf < 8; ++nf) {
                    const uint32_t* bl = &b_lo[nf >> 1][(nf & 1) * 2];
                    mma_bf16(acc[mf][nf], a_hi[mf], bl[0], bl[1]);
                }
            // Pass 3: Alo*Bhi
#pragma unroll
            for (int mf = 0; mf < 2; ++mf)
#pragma unroll
                for (int nf = 0; nf < 8; ++nf) {
                    const uint32_t* bh = &b_hi[nf >> 1][(nf & 1) * 2];
                    mma_bf16(acc[mf][nf], a_lo[mf], bh[0], bh[1]);
                }
        }
    }

    // Epilogue
#pragma unroll
    for (int mf = 0; mf < 2; ++mf) {
        const int rbase = row0 + warp_m * 32 + mf * 16 + (lane >> 2);
#pragma unroll
        for (int nf = 0; nf < 8; ++nf) {
            const int col = col0 + warp_n * 64 + nf * 8 + (lane & 3) * 2;
            float2 bv = *(const float2*)&bias[col];
#pragma unroll
            for (int half = 0; half < 2; ++half) {
                const int m = rbase + half * 8;
                float2 w = { acc[mf][nf][half * 2 + 0] + bv.x,
                             acc[mf][nf][half * 2 + 1] + bv.y };
                if (MODE == 1) {
                    *(float2*)(out + (size_t)m * HID + col) = w;
                } else {
                    const int which = col0 >> 11;
                    const int h = (col0 & 2047) >> 7;
                    const int d = col & 127;
                    float* base = (which == 0) ? g_q : (which == 1) ? g_k : g_v;
                    const int b = m >> 11, sI = m & 2047;
                    *(float2*)(base + ((size_t)(b * NHEADS + h) * SEQ + sI) * HDIM + d) = w;
                }
            }
        }
    }
}

// ---------------------------------------------------------------------------
// Flash attention (fp32, causal). Epilogue writes bf16 hi/lo directly
// (consumed by the out-proj GEMM) — no fp32 intermediate round-trip.
// ---------------------------------------------------------------------------
#define FLASH_SMEM_FLOATS (64*128 + 64*129 + 64*128 + 64*65 + 3*64)
#define FLASH_SMEM_BYTES  (FLASH_SMEM_FLOATS * 4)

__global__ void flash_kernel()
{
    const int qtile = (int)gridDim.x - 1 - (int)blockIdx.x;
    const int bh    = blockIdx.y;
    const float* Q = g_q + (size_t)bh * SEQ * HDIM;
    const float* K = g_k + (size_t)bh * SEQ * HDIM;
    const float* V = g_v + (size_t)bh * SEQ * HDIM;

    extern __shared__ float sm[];
    float* sQ = sm;
    float* sK = sQ + 64 * 128;
    float* sV = sK + 64 * 129;
    float* sP = sV + 64 * 128;
    float* sM = sP + 64 * 65;
    float* sL = sM + 64;
    float* sA = sL + 64;

    const int tid = threadIdx.x;
    const int tx  = tid & 15;
    const int ty  = tid >> 4;

    for (int i = tid; i < 64 * 32; i += 256) {
        int r = i >> 5, c = (i & 31) << 2;
        *(float4*)&sQ[r * 128 + c] =
            *(const float4*)&Q[(size_t)(qtile * 64 + r) * HDIM + c];
    }
    if (tid < 64) { sM[tid] = -1e30f; sL[tid] = 0.f; }

    float o[4][8];
#pragma unroll
    for (int r = 0; r < 4; r++)
#pragma unroll
        for (int c = 0; c < 8; c++) o[r][c] = 0.f;

    const float scale = 0.08838834764831845f;

    for (int kt = 0; kt <= qtile; kt++) {
        __syncthreads();
        for (int i = tid; i < 64 * 32; i += 256) {
            int r = i >> 5, c = (i & 31) << 2;
            float4 kv = *(const float4*)&K[(size_t)(kt * 64 + r) * HDIM + c];
            sK[r * 129 + c + 0] = kv.x; sK[r * 129 + c + 1] = kv.y;
            sK[r * 129 + c + 2] = kv.z; sK[r * 129 + c + 3] = kv.w;
            *(float4*)&sV[r * 128 + c] =
                *(const float4*)&V[(size_t)(kt * 64 + r) * HDIM + c];
        }
        __syncthreads();

        float s4[4][4];
#pragma unroll
        for (int r = 0; r < 4; r++)
#pragma unroll
            for (int c = 0; c < 4; c++) s4[r][c] = 0.f;

#pragma unroll 4
        for (int d = 0; d < 128; d++) {
            float qv[4], kv[4];
#pragma unroll
            for (int r = 0; r < 4; r++) qv[r] = sQ[(ty * 4 + r) * 128 + d];
#pragma unroll
            for (int c = 0; c < 4; c++) kv[c] = sK[(tx * 4 + c) * 129 + d];
#pragma unroll
            for (int r = 0; r < 4; r++)
#pragma unroll
                for (int c = 0; c < 4; c++)
                    s4[r][c] = fmaf(qv[r], kv[c], s4[r][c]);
        }

        const int qi = qtile * 64 + ty * 4;
        const int kj = kt * 64 + tx * 4;
#pragma unroll
        for (int r = 0; r < 4; r++)
#pragma unroll
            for (int c = 0; c < 4; c++) {
                float v = s4[r][c] * scale;
                if (kj + c > qi + r) v = -1e30f;
                sP[(ty * 4 + r) * 65 + tx * 4 + c] = v;
            }
        __syncthreads();

        if (tid < 64) {
            float mo = sM[tid];
            float rm = mo;
            for (int j = 0; j < 64; j++) rm = fmaxf(rm, sP[tid * 65 + j]);
            float alpha = __expf(mo - rm);
            float sum = 0.f;
            for (int j = 0; j < 64; j++) {
                float p = __expf(sP[tid * 65 + j] - rm);
                sP[tid * 65 + j] = p;
                sum += p;
            }
            sL[tid] = sL[tid] * alpha + sum;
            sM[tid] = rm;
            sA[tid] = alpha;
        }
        __syncthreads();

#pragma unroll
        for (int r = 0; r < 4; r++) {
            float a = sA[ty * 4 + r];
#pragma unroll
            for (int c = 0; c < 8; c++) o[r][c] *= a;
        }
#pragma unroll 2
        for (int k = 0; k < 64; k++) {
            float p0 = sP[(ty * 4 + 0) * 65 + k];
            float p1 = sP[(ty * 4 + 1) * 65 + k];
            float p2 = sP[(ty * 4 + 2) * 65 + k];
            float p3 = sP[(ty * 4 + 3) * 65 + k];
            float4 v0 = *(const float4*)&sV[k * 128 + tx * 8];
            float4 v1 = *(const float4*)&sV[k * 128 + tx * 8 + 4];
            o[0][0] = fmaf(p0, v0.x, o[0][0]); o[0][1] = fmaf(p0, v0.y, o[0][1]);
            o[0][2] = fmaf(p0, v0.z, o[0][2]); o[0][3] = fmaf(p0, v0.w, o[0][3]);
            o[0][4] = fmaf(p0, v1.x, o[0][4]); o[0][5] = fmaf(p0, v1.y, o[0][5]);
            o[0][6] = fmaf(p0, v1.z, o[0][6]); o[0][7] = fmaf(p0, v1.w, o[0][7]);
            o[1][0] = fmaf(p1, v0.x, o[1][0]); o[1][1] = fmaf(p1, v0.y, o[1][1]);
            o[1][2] = fmaf(p1, v0.z, o[1][2]); o[1][3] = fmaf(p1, v0.w, o[1][3]);
            o[1][4] = fmaf(p1, v1.x, o[1][4]); o[1][5] = fmaf(p1, v1.y, o[1][5]);
            o[1][6] = fmaf(p1, v1.z, o[1][6]); o[1][7] = fmaf(p1, v1.w, o[1][7]);
            o[2][0] = fmaf(p2, v0.x, o[2][0]); o[2][1] = fmaf(p2, v0.y, o[2][1]);
            o[2][2] = fmaf(p2, v0.z, o[2][2]); o[2][3] = fmaf(p2, v0.w, o[2][3]);
            o[2][4] = fmaf(p2, v1.x, o[2][4]); o[2][5] = fmaf(p2, v1.y, o[2][5]);
            o[2][6] = fmaf(p2, v1.z, o[2][6]); o[2][7] = fmaf(p2, v1.w, o[2][7]);
            o[3][0] = fmaf(p3, v0.x, o[3][0]); o[3][1] = fmaf(p3, v0.y, o[3][1]);
            o[3][2] = fmaf(p3, v0.z, o[3][2]); o[3][3] = fmaf(p3, v0.w, o[3][3]);
            o[3][4] = fmaf(p3, v1.x, o[3][4]); o[3][5] = fmaf(p3, v1.y, o[3][5]);
            o[3][6] = fmaf(p3, v1.z, o[3][6]); o[3][7] = fmaf(p3, v1.w, o[3][7]);
        }
    }

    // Normalize + decompose to bf16 hi/lo, write [B,S,H] layout
    const int b = bh >> 4, hd = bh & 15;
#pragma unroll
    for (int r = 0; r < 4; r++) {
        int i = ty * 4 + r;
        float inv = 1.f / sL[i];
        int sg = qtile * 64 + i;
        size_t base = ((size_t)(b * SEQ + sg)) * HID + hd * HDIM + tx * 8;
        uint32_t hp[4], lp[4];
#pragma unroll
        for (int c = 0; c < 4; c++) {
            float x0 = o[r][c * 2 + 0] * inv;
            float x1 = o[r][c * 2 + 1] * inv;
            __nv_bfloat162 h2 = __float22bfloat162_rn(make_float2(x0, x1));
            float2 hf = __bfloat1622float2(h2);
            __nv_bfloat162 l2 = __float22bfloat162_rn(make_float2(x0 - hf.x, x1 - hf.y));
            hp[c] = *(uint32_t*)&h2;
            lp[c] = *(uint32_t*)&l2;
        }
        *(uint4*)(g_attn_hi + base) = *(uint4*)hp;
        *(uint4*)(g_attn_lo + base) = *(uint4*)lp;
    }
}

// ---------------------------------------------------------------------------
extern "C" void kernel_launch(void* const* d_in, const int* in_sizes, int n_in,
                              void* d_out, int out_size)
{
    const float* hs    = (const float*)d_in[0];
    const float* W_in  = (const float*)d_in[1];
    const float* b_in  = (const float*)d_in[2];
    const float* W_out = (const float*)d_in[3];
    const float* b_out = (const float*)d_in[4];
    float* out = (float*)d_out;
    (void)in_sizes; (void)n_in; (void)out_size;

    cudaFuncSetAttribute(gemm_mma_kernel<0, HID>,
                         cudaFuncAttributeMaxDynamicSharedMemorySize, GEMM_SMEM);
    cudaFuncSetAttribute(gemm_mma_kernel<1, HID>,
                         cudaFuncAttributeMaxDynamicSharedMemorySize, GEMM_SMEM);
    cudaFuncSetAttribute(flash_kernel,
                         cudaFuncAttributeMaxDynamicSharedMemorySize, FLASH_SMEM_BYTES);

    __nv_bfloat16 *hs_hi, *hs_lo, *win_hi, *win_lo, *wout_hi, *wout_lo, *at_hi, *at_lo;
    cudaGetSymbolAddress((void**)&hs_hi,  g_hs_hi);
    cudaGetSymbolAddress((void**)&hs_lo,  g_hs_lo);
    cudaGetSymbolAddress((void**)&win_hi, g_win_hi);
    cudaGetSymbolAddress((void**)&win_lo, g_win_lo);
    cudaGetSymbolAddress((void**)&wout_hi, g_wout_hi);
    cudaGetSymbolAddress((void**)&wout_lo, g_wout_lo);
    cudaGetSymbolAddress((void**)&at_hi,  g_attn_hi);
    cudaGetSymbolAddress((void**)&at_lo,  g_attn_lo);

    // 0) fp32 -> bf16 hi/lo decompositions
    cvt_hilo_kernel<<<2048, 256>>>(hs,    hs_hi,  hs_lo,  MROWS * HID / 4);
    cvt_hilo_kernel<<<2048, 256>>>(W_in,  win_hi, win_lo, NQKV * HID / 4);
    cvt_hilo_kernel<<<2048, 256>>>(W_out, wout_hi, wout_lo, HID * HID / 4);

    // 1) QKV projection (HMMA bf16x3), scatter to head layout
    gemm_mma_kernel<0, HID><<<dim3(NQKV / 128, MROWS / 128), 256, GEMM_SMEM>>>(
        hs_hi, hs_lo, win_hi, win_lo, b_in, nullptr);

    // 2) causal flash attention -> g_attn_hi/lo [B,S,H]
    flash_kernel<<<dim3(SEQ / 64, BATCH * NHEADS), 256, FLASH_SMEM_BYTES>>>();

    // 3) output projection -> d_out
    gemm_mma_kernel<1, HID><<<dim3(HID / 128, MROWS / 128), 256, GEMM_SMEM>>>(
        at_hi, at_lo, wout_hi, wout_lo, b_out, out);
}

// round 5
// speedup vs baseline: 3.4887x; 1.8964x over previous
#include <cuda_runtime.h>
#include <cuda_bf16.h>
#include <cstdint>

// Problem constants
#define BATCH   2
#define SEQ     2048
#define HID     2048
#define NHEADS  16
#define HDIM    128
#define MROWS   (BATCH*SEQ)      // 4096
#define NQKV    (3*HID)          // 6144

// Scratch (device globals: allocation-free) — all bf16 hi/lo pairs
__device__ __nv_bfloat16 g_qh[(size_t)BATCH*NHEADS*SEQ*HDIM], g_ql[(size_t)BATCH*NHEADS*SEQ*HDIM];
__device__ __nv_bfloat16 g_kh[(size_t)BATCH*NHEADS*SEQ*HDIM], g_kl[(size_t)BATCH*NHEADS*SEQ*HDIM];
__device__ __nv_bfloat16 g_vh[(size_t)BATCH*NHEADS*SEQ*HDIM], g_vl[(size_t)BATCH*NHEADS*SEQ*HDIM];
__device__ __nv_bfloat16 g_hs_hi[(size_t)MROWS*HID],   g_hs_lo[(size_t)MROWS*HID];
__device__ __nv_bfloat16 g_win_hi[(size_t)NQKV*HID],   g_win_lo[(size_t)NQKV*HID];
__device__ __nv_bfloat16 g_wout_hi[(size_t)HID*HID],   g_wout_lo[(size_t)HID*HID];
__device__ __nv_bfloat16 g_attn_hi[(size_t)MROWS*HID], g_attn_lo[(size_t)MROWS*HID];

__device__ __forceinline__ uint32_t smem_to_u32(const void* p) {
    uint32_t a;
    asm("{ .reg .u64 t; cvta.to.shared.u64 t, %1; cvt.u32.u64 %0, t; }"
        : "=r"(a) : "l"(p));
    return a;
}
__device__ __forceinline__ void ldsm_x4(uint32_t* r, uint32_t addr) {
    asm volatile("ldmatrix.sync.aligned.m8n8.x4.shared.b16 {%0,%1,%2,%3}, [%4];"
                 : "=r"(r[0]), "=r"(r[1]), "=r"(r[2]), "=r"(r[3]) : "r"(addr));
}
__device__ __forceinline__ void ldsm_x4t(uint32_t* r, uint32_t addr) {
    asm volatile("ldmatrix.sync.aligned.m8n8.x4.trans.shared.b16 {%0,%1,%2,%3}, [%4];"
                 : "=r"(r[0]), "=r"(r[1]), "=r"(r[2]), "=r"(r[3]) : "r"(addr));
}
__device__ __forceinline__ void mma_bf16(float* d, const uint32_t* a,
                                         uint32_t b0, uint32_t b1) {
    asm volatile("mma.sync.aligned.m16n8k16.row.col.f32.bf16.bf16.f32 "
                 "{%0,%1,%2,%3}, {%4,%5,%6,%7}, {%8,%9}, {%0,%1,%2,%3};"
                 : "+f"(d[0]), "+f"(d[1]), "+f"(d[2]), "+f"(d[3])
                 : "r"(a[0]), "r"(a[1]), "r"(a[2]), "r"(a[3]), "r"(b0), "r"(b1));
}
__device__ __forceinline__ void cp_async16(uint32_t dst, const void* src) {
    asm volatile("cp.async.cg.shared.global [%0], [%1], 16;" :: "r"(dst), "l"(src));
}
// split fp32 pair -> bf16 hi pair + lo pair (packed)
__device__ __forceinline__ uint32_t pack_hilo(float x0, float x1, uint32_t& lo) {
    __nv_bfloat162 h = __float22bfloat162_rn(make_float2(x0, x1));
    float2 hf = __bfloat1622float2(h);
    __nv_bfloat162 l = __float22bfloat162_rn(make_float2(x0 - hf.x, x1 - hf.y));
    lo = *(uint32_t*)&l;
    return *(uint32_t*)&h;
}

// ---------------------------------------------------------------------------
// fp32 -> bf16 hi/lo conversion (grid-stride, vectorized)
// ---------------------------------------------------------------------------
__global__ void cvt_hilo_kernel(const float* __restrict__ src,
                                __nv_bfloat16* __restrict__ hi,
                                __nv_bfloat16* __restrict__ lo,
                                int n4)
{
    for (int i = blockIdx.x * blockDim.x + threadIdx.x; i < n4;
         i += gridDim.x * blockDim.x) {
        float4 v = ((const float4*)src)[i];
        uint2 hp, lp;
        hp.x = pack_hilo(v.x, v.y, lp.x);
        hp.y = pack_hilo(v.z, v.w, lp.y);
        ((uint2*)hi)[i] = hp;
        ((uint2*)lo)[i] = lp;
    }
}

// ---------------------------------------------------------------------------
// HMMA GEMM (bf16x3): out[m,n] = sum_k A[m,k]*W[n,k] + bias[n]
// MODE 0: write q/k/v as bf16 hi/lo in head layout;  MODE 1: fp32 to out.
// ---------------------------------------------------------------------------
#define ROWB 144
#define TILE_B (128*ROWB)
#define AT_HI 0
#define AT_LO TILE_B
#define BT_HI (2*TILE_B)
#define BT_LO (3*TILE_B)
#define STAGE_B (4*TILE_B)
#define GEMM_SMEM (2*STAGE_B)

template<int MODE, int KDIM>
__global__ __launch_bounds__(256, 1)
void gemm_mma_kernel(const __nv_bfloat16* __restrict__ Ah,
                     const __nv_bfloat16* __restrict__ Al,
                     const __nv_bfloat16* __restrict__ Bh,
                     const __nv_bfloat16* __restrict__ Bl,
                     const float* __restrict__ bias,
                     float* __restrict__ out)
{
    extern __shared__ char smem[];
    const uint32_t smb = smem_to_u32(smem);
    const int tid  = threadIdx.x;
    const int wid  = tid >> 5;
    const int lane = tid & 31;
    const int warp_m = wid & 3;
    const int warp_n = wid >> 2;
    const int row0 = blockIdx.y * 128;
    const int col0 = blockIdx.x * 128;
    constexpr int NCHUNK = KDIM / 64;

    const __nv_bfloat16* srcs[4] = {
        Ah + (size_t)row0 * KDIM, Al + (size_t)row0 * KDIM,
        Bh + (size_t)col0 * KDIM, Bl + (size_t)col0 * KDIM };

    auto issue = [&](int c, int st) {
        const int k0 = c * 64;
        const uint32_t sb = smb + st * STAGE_B;
#pragma unroll
        for (int t = 0; t < 4; ++t) {
            const __nv_bfloat16* s = srcs[t];
            const uint32_t db = sb + t * TILE_B;
#pragma unroll
            for (int i = 0; i < 4; ++i) {
                int idx = i * 256 + tid;
                int row = idx >> 3, ch = idx & 7;
                cp_async16(db + row * ROWB + ch * 16,
                           s + (size_t)row * KDIM + k0 + ch * 8);
            }
        }
    };

    float acc[2][8][4];
#pragma unroll
    for (int i = 0; i < 2; i++)
#pragma unroll
        for (int j = 0; j < 8; j++)
#pragma unroll
            for (int q = 0; q < 4; q++) acc[i][j][q] = 0.f;

    const int rowA = (lane & 7) + ((lane >> 3) & 1) * 8;
    const int kA   = (lane >> 4) * 8;
    const int rowB = (lane & 7) + (lane >> 4) * 8;
    const int kB   = ((lane >> 3) & 1) * 8;

    issue(0, 0);
    asm volatile("cp.async.commit_group;");

    for (int c = 0; c < NCHUNK; ++c) {
        __syncthreads();
        if (c + 1 < NCHUNK) issue(c + 1, (c + 1) & 1);
        asm volatile("cp.async.commit_group;");
        asm volatile("cp.async.wait_group 1;");
        __syncthreads();

        const uint32_t sb = smb + (c & 1) * STAGE_B;
        uint32_t aBase[2], bBase[4];
#pragma unroll
        for (int mf = 0; mf < 2; ++mf)
            aBase[mf] = sb + (warp_m * 32 + mf * 16 + rowA) * ROWB + kA * 2;
#pragma unroll
        for (int nf = 0; nf < 4; ++nf)
            bBase[nf] = sb + BT_HI + (warp_n * 64 + nf * 16 + rowB) * ROWB + kB * 2;

#pragma unroll
        for (int ks = 0; ks < 4; ++ks) {
            const int kb2 = ks * 32;
            uint32_t a_hi[2][4], a_lo[2][4];
#pragma unroll
            for (int mf = 0; mf < 2; ++mf) {
                ldsm_x4(a_hi[mf], aBase[mf] + AT_HI + kb2);
                ldsm_x4(a_lo[mf], aBase[mf] + AT_LO + kb2);
            }
            uint32_t b_hi[4][4], b_lo[4][4];
#pragma unroll
            for (int nf = 0; nf < 4; ++nf) {
                ldsm_x4(b_hi[nf], bBase[nf] + kb2);
                ldsm_x4(b_lo[nf], bBase[nf] + TILE_B + kb2);
            }
#pragma unroll
            for (int mf = 0; mf < 2; ++mf)
#pragma unroll
                for (int nf = 0; nf < 8; ++nf) {
                    const uint32_t* bh = &b_hi[nf >> 1][(nf & 1) * 2];
                    mma_bf16(acc[mf][nf], a_hi[mf], bh[0], bh[1]);
                }
#pragma unroll
            for (int mf = 0; mf < 2; ++mf)
#pragma unroll
                for (int nf = 0; nf < 8; ++nf) {
                    const uint32_t* bl = &b_lo[nf >> 1][(nf & 1) * 2];
                    mma_bf16(acc[mf][nf], a_hi[mf], bl[0], bl[1]);
                }
#pragma unroll
            for (int mf = 0; mf < 2; ++mf)
#pragma unroll
                for (int nf = 0; nf < 8; ++nf) {
                    const uint32_t* bh = &b_hi[nf >> 1][(nf & 1) * 2];
                    mma_bf16(acc[mf][nf], a_lo[mf], bh[0], bh[1]);
                }
        }
    }

    // Epilogue
#pragma unroll
    for (int mf = 0; mf < 2; ++mf) {
        const int rbase = row0 + warp_m * 32 + mf * 16 + (lane >> 2);
#pragma unroll
        for (int nf = 0; nf < 8; ++nf) {
            const int col = col0 + warp_n * 64 + nf * 8 + (lane & 3) * 2;
            float2 bv = *(const float2*)&bias[col];
#pragma unroll
            for (int half = 0; half < 2; ++half) {
                const int m = rbase + half * 8;
                float wx = acc[mf][nf][half * 2 + 0] + bv.x;
                float wy = acc[mf][nf][half * 2 + 1] + bv.y;
                if (MODE == 1) {
                    float2 w = {wx, wy};
                    *(float2*)(out + (size_t)m * HID + col) = w;
                } else {
                    const int which = col0 >> 11;            // 0=q 1=k 2=v
                    const int h = (col0 & 2047) >> 7;
                    const int d = col & 127;
                    __nv_bfloat16* dh = (which == 0) ? g_qh : (which == 1) ? g_kh : g_vh;
                    __nv_bfloat16* dl = (which == 0) ? g_ql : (which == 1) ? g_kl : g_vl;
                    const int b = m >> 11, sI = m & 2047;
                    size_t off = ((size_t)(b * NHEADS + h) * SEQ + sI) * HDIM + d;
                    uint32_t lo;
                    uint32_t hi = pack_hilo(wx, wy, lo);
                    *(uint32_t*)(dh + off) = hi;
                    *(uint32_t*)(dl + off) = lo;
                }
            }
        }
    }
}

// ---------------------------------------------------------------------------
// Flash attention on HMMA (bf16x3, causal).
// Block: 256 thr (8 warps), q-tile 128 rows (16/warp), k-tiles 64,
// cp.async double-buffered K/V stages. Writes g_attn hi/lo in [B,S,H].
// ---------------------------------------------------------------------------
#define FROWB 272                       // 128 bf16 = 256B + 16 pad
#define FQH_OFF 0
#define FQL_OFF (128*FROWB)             // 34816
#define FSTAGE_OFF (2*128*FROWB)        // 69632
#define FKH 0
#define FKL (64*FROWB)
#define FVH (2*64*FROWB)
#define FVL (3*64*FROWB)
#define FSTAGE_B (4*64*FROWB)           // 69632
#define FLASH_SMEM (FSTAGE_OFF + 2*FSTAGE_B)   // 208896

__global__ __launch_bounds__(256, 1) void flash_mma_kernel()
{
    extern __shared__ char smem[];
    const uint32_t smb = smem_to_u32(smem);
    const int qt  = (int)gridDim.x - 1 - (int)blockIdx.x;   // heavy-first
    const int bh  = blockIdx.y;
    const int tid = threadIdx.x, wid = tid >> 5, lane = tid & 31;

    const size_t tb = (size_t)bh * SEQ * HDIM;
    const __nv_bfloat16 *Qh = g_qh + tb, *Ql = g_ql + tb;
    const __nv_bfloat16 *Kh = g_kh + tb, *Kl = g_kl + tb;
    const __nv_bfloat16 *Vh = g_vh + tb, *Vl = g_vl + tb;

    const int ktmax = 2 * qt + 1;

    auto issue_kv = [&](int kt, int st) {
        const uint32_t sb = smb + FSTAGE_OFF + st * FSTAGE_B;
        const __nv_bfloat16* srcs[4] = {Kh, Kl, Vh, Vl};
#pragma unroll
        for (int t = 0; t < 4; ++t) {
#pragma unroll
            for (int i = 0; i < 4; ++i) {
                int idx = i * 256 + tid;
                int r = idx >> 4, ch = idx & 15;
                cp_async16(sb + t * (64 * FROWB) + r * FROWB + ch * 16,
                           srcs[t] + (size_t)(kt * 64 + r) * HDIM + ch * 8);
            }
        }
    };

    // Prologue: Q tile + KV stage 0
#pragma unroll
    for (int i = 0; i < 8; ++i) {
        int idx = i * 256 + tid;
        int r = idx >> 4, ch = idx & 15;
        size_t g = (size_t)(qt * 128 + r) * HDIM + ch * 8;
        cp_async16(smb + FQH_OFF + r * FROWB + ch * 16, Qh + g);
        cp_async16(smb + FQL_OFF + r * FROWB + ch * 16, Ql + g);
    }
    issue_kv(0, 0);
    asm volatile("cp.async.commit_group;");

    // ldmatrix lane address components
    const uint32_t qaH = smb + FQH_OFF +
        (uint32_t)(wid * 16 + (lane & 7) + ((lane >> 3) & 1) * 8) * FROWB + (lane >> 4) * 16;
    const uint32_t qaL = qaH + (FQL_OFF - FQH_OFF);
    const uint32_t koff = (uint32_t)((lane & 7) + (lane >> 4) * 8) * FROWB
                        + ((lane >> 3) & 1) * 16;
    const uint32_t voff = (uint32_t)((lane & 7) + ((lane >> 3) & 1) * 8) * FROWB
                        + (lane >> 4) * 16;

    float o[16][4];
#pragma unroll
    for (int i = 0; i < 16; i++)
#pragma unroll
        for (int j = 0; j < 4; j++) o[i][j] = 0.f;
    float m0 = -1e30f, m1 = -1e30f, l0 = 0.f, l1 = 0.f;
    const float scale = 0.08838834764831845f;   // 1/sqrt(128)

    const int wrow = qt * 128 + wid * 16;       // warp's first q row
    const int r0g = wrow + (lane >> 2);
    const int r1g = r0g + 8;

    for (int kt = 0; kt <= ktmax; ++kt) {
        const int cur = kt & 1;
        __syncthreads();                         // prev compute done; other buf free
        if (kt < ktmax) issue_kv(kt + 1, cur ^ 1);
        asm volatile("cp.async.commit_group;");
        asm volatile("cp.async.wait_group 1;");
        __syncthreads();

        const bool active = (kt * 64 <= wrow + 15);
        if (active) {
            const uint32_t sb = smb + FSTAGE_OFF + cur * FSTAGE_B;
            // ---- S = Q K^T (bf16x3) ----
            float s[8][4];
#pragma unroll
            for (int i = 0; i < 8; i++)
#pragma unroll
                for (int j = 0; j < 4; j++) s[i][j] = 0.f;
#pragma unroll
            for (int ks = 0; ks < 8; ++ks) {
                uint32_t qh[4], ql[4];
                ldsm_x4(qh, qaH + ks * 32);
                ldsm_x4(ql, qaL + ks * 32);
                uint32_t kh[4][4], kl[4][4];
#pragma unroll
                for (int c = 0; c < 4; ++c) {
                    ldsm_x4(kh[c], sb + FKH + koff + c * (16 * FROWB) + ks * 32);
                    ldsm_x4(kl[c], sb + FKL + koff + c * (16 * FROWB) + ks * 32);
                }
#pragma unroll
                for (int c = 0; c < 4; ++c) {
                    mma_bf16(s[2*c],   qh, kh[c][0], kh[c][1]);
                    mma_bf16(s[2*c+1], qh, kh[c][2], kh[c][3]);
                }
#pragma unroll
                for (int c = 0; c < 4; ++c) {
                    mma_bf16(s[2*c],   qh, kl[c][0], kl[c][1]);
                    mma_bf16(s[2*c+1], qh, kl[c][2], kl[c][3]);
                }
#pragma unroll
                for (int c = 0; c < 4; ++c) {
                    mma_bf16(s[2*c],   ql, kh[c][0], kh[c][1]);
                    mma_bf16(s[2*c+1], ql, kh[c][2], kh[c][3]);
                }
            }
            // ---- scale + causal mask ----
            const bool needmask = (kt * 64 + 63 > wrow);
#pragma unroll
            for (int nf = 0; nf < 8; ++nf) {
                const int kc = kt * 64 + nf * 8 + (lane & 3) * 2;
                s[nf][0] *= scale; s[nf][1] *= scale;
                s[nf][2] *= scale; s[nf][3] *= scale;
                if (needmask) {
                    if (kc     > r0g) s[nf][0] = -1e30f;
                    if (kc + 1 > r0g) s[nf][1] = -1e30f;
                    if (kc     > r1g) s[nf][2] = -1e30f;
                    if (kc + 1 > r1g) s[nf][3] = -1e30f;
                }
            }
            // ---- online softmax ----
            float mx0 = m0, mx1 = m1;
#pragma unroll
            for (int nf = 0; nf < 8; ++nf) {
                mx0 = fmaxf(mx0, fmaxf(s[nf][0], s[nf][1]));
                mx1 = fmaxf(mx1, fmaxf(s[nf][2], s[nf][3]));
            }
            mx0 = fmaxf(mx0, __shfl_xor_sync(0xffffffffu, mx0, 1));
            mx0 = fmaxf(mx0, __shfl_xor_sync(0xffffffffu, mx0, 2));
            mx1 = fmaxf(mx1, __shfl_xor_sync(0xffffffffu, mx1, 1));
            mx1 = fmaxf(mx1, __shfl_xor_sync(0xffffffffu, mx1, 2));
            const float a0 = __expf(m0 - mx0), a1 = __expf(m1 - mx1);
            m0 = mx0; m1 = mx1;
            float sum0 = 0.f, sum1 = 0.f;
#pragma unroll
            for (int nf = 0; nf < 8; ++nf) {
                s[nf][0] = __expf(s[nf][0] - mx0);
                s[nf][1] = __expf(s[nf][1] - mx0);
                s[nf][2] = __expf(s[nf][2] - mx1);
                s[nf][3] = __expf(s[nf][3] - mx1);
                sum0 += s[nf][0] + s[nf][1];
                sum1 += s[nf][2] + s[nf][3];
            }
            sum0 += __shfl_xor_sync(0xffffffffu, sum0, 1);
            sum0 += __shfl_xor_sync(0xffffffffu, sum0, 2);
            sum1 += __shfl_xor_sync(0xffffffffu, sum1, 1);
            sum1 += __shfl_xor_sync(0xffffffffu, sum1, 2);
            l0 = l0 * a0 + sum0;
            l1 = l1 * a1 + sum1;
#pragma unroll
            for (int nf = 0; nf < 16; ++nf) {
                o[nf][0] *= a0; o[nf][1] *= a0;
                o[nf][2] *= a1; o[nf][3] *= a1;
            }
            // ---- O += P V (bf16x3) ----
#pragma unroll
            for (int ks2 = 0; ks2 < 4; ++ks2) {
                uint32_t ah[4], al[4];
                ah[0] = pack_hilo(s[2*ks2][0],   s[2*ks2][1],   al[0]);
                ah[1] = pack_hilo(s[2*ks2][2],   s[2*ks2][3],   al[1]);
                ah[2] = pack_hilo(s[2*ks2+1][0], s[2*ks2+1][1], al[2]);
                ah[3] = pack_hilo(s[2*ks2+1][2], s[2*ks2+1][3], al[3]);
#pragma unroll
                for (int dp = 0; dp < 4; ++dp) {
                    uint32_t v0h[4], v0l[4], v1h[4], v1l[4];
                    const uint32_t vb = sb + voff + ks2 * (16 * FROWB) + dp * 64;
                    ldsm_x4t(v0h, vb + FVH);
                    ldsm_x4t(v0l, vb + FVL);
                    ldsm_x4t(v1h, vb + FVH + 32);
                    ldsm_x4t(v1l, vb + FVL + 32);
                    float* o0 = o[4*dp + 0];
                    float* o1 = o[4*dp + 1];
                    float* o2 = o[4*dp + 2];
                    float* o3 = o[4*dp + 3];
                    mma_bf16(o0, ah, v0h[0], v0h[1]);
                    mma_bf16(o1, ah, v0h[2], v0h[3]);
                    mma_bf16(o2, ah, v1h[0], v1h[1]);
                    mma_bf16(o3, ah, v1h[2], v1h[3]);
                    mma_bf16(o0, ah, v0l[0], v0l[1]);
                    mma_bf16(o1, ah, v0l[2], v0l[3]);
                    mma_bf16(o2, ah, v1l[0], v1l[1]);
                    mma_bf16(o3, ah, v1l[2], v1l[3]);
                    mma_bf16(o0, al, v0h[0], v0h[1]);
                    mma_bf16(o1, al, v0h[2], v0h[3]);
                    mma_bf16(o2, al, v1h[0], v1h[1]);
                    mma_bf16(o3, al, v1h[2], v1h[3]);
                }
            }
        }
    }

    // ---- normalize + write bf16 hi/lo to g_attn [B,S,H] ----
    const float inv0 = 1.f / l0, inv1 = 1.f / l1;
    const int b = bh >> 4, hd = bh & 15;
    const size_t ob0 = ((size_t)(b * SEQ + r0g)) * HID + hd * HDIM;
    const size_t ob1 = ob0 + (size_t)8 * HID;
#pragma unroll
    for (int nf = 0; nf < 16; ++nf) {
        const int col = nf * 8 + (lane & 3) * 2;
        uint32_t lo;
        uint32_t hi = pack_hilo(o[nf][0] * inv0, o[nf][1] * inv0, lo);
        *(uint32_t*)(g_attn_hi + ob0 + col) = hi;
        *(uint32_t*)(g_attn_lo + ob0 + col) = lo;
        hi = pack_hilo(o[nf][2] * inv1, o[nf][3] * inv1, lo);
        *(uint32_t*)(g_attn_hi + ob1 + col) = hi;
        *(uint32_t*)(g_attn_lo + ob1 + col) = lo;
    }
}

// ---------------------------------------------------------------------------
extern "C" void kernel_launch(void* const* d_in, const int* in_sizes, int n_in,
                              void* d_out, int out_size)
{
    const float* hs    = (const float*)d_in[0];
    const float* W_in  = (const float*)d_in[1];
    const float* b_in  = (const float*)d_in[2];
    const float* W_out = (const float*)d_in[3];
    const float* b_out = (const float*)d_in[4];
    float* out = (float*)d_out;
    (void)in_sizes; (void)n_in; (void)out_size;

    cudaFuncSetAttribute(gemm_mma_kernel<0, HID>,
                         cudaFuncAttributeMaxDynamicSharedMemorySize, GEMM_SMEM);
    cudaFuncSetAttribute(gemm_mma_kernel<1, HID>,
                         cudaFuncAttributeMaxDynamicSharedMemorySize, GEMM_SMEM);
    cudaFuncSetAttribute(flash_mma_kernel,
                         cudaFuncAttributeMaxDynamicSharedMemorySize, FLASH_SMEM);

    __nv_bfloat16 *hs_hi, *hs_lo, *win_hi, *win_lo, *wout_hi, *wout_lo, *at_hi, *at_lo;
    cudaGetSymbolAddress((void**)&hs_hi,   g_hs_hi);
    cudaGetSymbolAddress((void**)&hs_lo,   g_hs_lo);
    cudaGetSymbolAddress((void**)&win_hi,  g_win_hi);
    cudaGetSymbolAddress((void**)&win_lo,  g_win_lo);
    cudaGetSymbolAddress((void**)&wout_hi, g_wout_hi);
    cudaGetSymbolAddress((void**)&wout_lo, g_wout_lo);
    cudaGetSymbolAddress((void**)&at_hi,   g_attn_hi);
    cudaGetSymbolAddress((void**)&at_lo,   g_attn_lo);

    // 0) fp32 -> bf16 hi/lo decompositions
    cvt_hilo_kernel<<<2048, 256>>>(hs,    hs_hi,   hs_lo,   MROWS * HID / 4);
    cvt_hilo_kernel<<<2048, 256>>>(W_in,  win_hi,  win_lo,  NQKV * HID / 4);
    cvt_hilo_kernel<<<2048, 256>>>(W_out, wout_hi, wout_lo, HID * HID / 4);

    // 1) QKV projection (HMMA bf16x3) -> q/k/v bf16 hi/lo head layout
    gemm_mma_kernel<0, HID><<<dim3(NQKV / 128, MROWS / 128), 256, GEMM_SMEM>>>(
        hs_hi, hs_lo, win_hi, win_lo, b_in, nullptr);

    // 2) causal flash attention (HMMA bf16x3) -> g_attn hi/lo [B,S,H]
    flash_mma_kernel<<<dim3(SEQ / 128, BATCH * NHEADS), 256, FLASH_SMEM>>>();

    // 3) output projection (HMMA bf16x3) -> d_out
    gemm_mma_kernel<1, HID><<<dim3(HID / 128, MROWS / 128), 256, GEMM_SMEM>>>(
        at_hi, at_lo, wout_hi, wout_lo, b_out, out);
}

// round 6
// speedup vs baseline: 3.5239x; 1.0101x over previous
#include <cuda_runtime.h>
#include <cuda_bf16.h>
#include <cstdint>

// Problem constants
#define BATCH   2
#define SEQ     2048
#define HID     2048
#define NHEADS  16
#define HDIM    128
#define MROWS   (BATCH*SEQ)      // 4096
#define NQKV    (3*HID)          // 6144

// Scratch (device globals: allocation-free) — all bf16 hi/lo pairs
__device__ __nv_bfloat16 g_qh[(size_t)BATCH*NHEADS*SEQ*HDIM], g_ql[(size_t)BATCH*NHEADS*SEQ*HDIM];
__device__ __nv_bfloat16 g_kh[(size_t)BATCH*NHEADS*SEQ*HDIM], g_kl[(size_t)BATCH*NHEADS*SEQ*HDIM];
__device__ __nv_bfloat16 g_vh[(size_t)BATCH*NHEADS*SEQ*HDIM], g_vl[(size_t)BATCH*NHEADS*SEQ*HDIM];
__device__ __nv_bfloat16 g_hs_hi[(size_t)MROWS*HID],   g_hs_lo[(size_t)MROWS*HID];
__device__ __nv_bfloat16 g_win_hi[(size_t)NQKV*HID],   g_win_lo[(size_t)NQKV*HID];
__device__ __nv_bfloat16 g_wout_hi[(size_t)HID*HID],   g_wout_lo[(size_t)HID*HID];
__device__ __nv_bfloat16 g_attn_hi[(size_t)MROWS*HID], g_attn_lo[(size_t)MROWS*HID];

__device__ __forceinline__ uint32_t smem_to_u32(const void* p) {
    uint32_t a;
    asm("{ .reg .u64 t; cvta.to.shared.u64 t, %1; cvt.u32.u64 %0, t; }"
        : "=r"(a) : "l"(p));
    return a;
}
__device__ __forceinline__ void ldsm_x4(uint32_t* r, uint32_t addr) {
    asm volatile("ldmatrix.sync.aligned.m8n8.x4.shared.b16 {%0,%1,%2,%3}, [%4];"
                 : "=r"(r[0]), "=r"(r[1]), "=r"(r[2]), "=r"(r[3]) : "r"(addr));
}
__device__ __forceinline__ void ldsm_x4t(uint32_t* r, uint32_t addr) {
    asm volatile("ldmatrix.sync.aligned.m8n8.x4.trans.shared.b16 {%0,%1,%2,%3}, [%4];"
                 : "=r"(r[0]), "=r"(r[1]), "=r"(r[2]), "=r"(r[3]) : "r"(addr));
}
__device__ __forceinline__ void mma_bf16(float* d, const uint32_t* a,
                                         uint32_t b0, uint32_t b1) {
    asm volatile("mma.sync.aligned.m16n8k16.row.col.f32.bf16.bf16.f32 "
                 "{%0,%1,%2,%3}, {%4,%5,%6,%7}, {%8,%9}, {%0,%1,%2,%3};"
                 : "+f"(d[0]), "+f"(d[1]), "+f"(d[2]), "+f"(d[3])
                 : "r"(a[0]), "r"(a[1]), "r"(a[2]), "r"(a[3]), "r"(b0), "r"(b1));
}
__device__ __forceinline__ void cp_async16(uint32_t dst, const void* src) {
    asm volatile("cp.async.cg.shared.global [%0], [%1], 16;" :: "r"(dst), "l"(src));
}
#define CP_COMMIT()  asm volatile("cp.async.commit_group;")
#define CP_WAIT(n)   asm volatile("cp.async.wait_group %0;" :: "n"(n))

// split fp32 pair -> bf16 hi pair + lo pair (packed)
__device__ __forceinline__ uint32_t pack_hilo(float x0, float x1, uint32_t& lo) {
    __nv_bfloat162 h = __float22bfloat162_rn(make_float2(x0, x1));
    float2 hf = __bfloat1622float2(h);
    __nv_bfloat162 l = __float22bfloat162_rn(make_float2(x0 - hf.x, x1 - hf.y));
    lo = *(uint32_t*)&l;
    return *(uint32_t*)&h;
}

// ---------------------------------------------------------------------------
// fp32 -> bf16 hi/lo conversion
// ---------------------------------------------------------------------------
__global__ void cvt_hilo_kernel(const float* __restrict__ src,
                                __nv_bfloat16* __restrict__ hi,
                                __nv_bfloat16* __restrict__ lo,
                                int n4)
{
    for (int i = blockIdx.x * blockDim.x + threadIdx.x; i < n4;
         i += gridDim.x * blockDim.x) {
        float4 v = ((const float4*)src)[i];
        uint2 hp, lp;
        hp.x = pack_hilo(v.x, v.y, lp.x);
        hp.y = pack_hilo(v.z, v.w, lp.y);
        ((uint2*)hi)[i] = hp;
        ((uint2*)lo)[i] = lp;
    }
}

// ---------------------------------------------------------------------------
// HMMA GEMM (bf16x3): out[m,n] = sum_k A[m,k]*W[n,k] + bias[n]
// 3-stage cp.async pipeline, ONE __syncthreads per K-chunk.
// ---------------------------------------------------------------------------
#define ROWB 144
#define TILE_B (128*ROWB)
#define AT_HI 0
#define AT_LO TILE_B
#define BT_HI (2*TILE_B)
#define BT_LO (3*TILE_B)
#define STAGE_B (4*TILE_B)        // 73728
#define GEMM_SMEM (3*STAGE_B)     // 221184

template<int MODE, int KDIM>
__global__ __launch_bounds__(256, 1)
void gemm_mma_kernel(const __nv_bfloat16* __restrict__ Ah,
                     const __nv_bfloat16* __restrict__ Al,
                     const __nv_bfloat16* __restrict__ Bh,
                     const __nv_bfloat16* __restrict__ Bl,
                     const float* __restrict__ bias,
                     float* __restrict__ out)
{
    extern __shared__ char smem[];
    const uint32_t smb = smem_to_u32(smem);
    const int tid  = threadIdx.x;
    const int wid  = tid >> 5;
    const int lane = tid & 31;
    const int warp_m = wid & 3;
    const int warp_n = wid >> 2;
    const int row0 = blockIdx.y * 128;
    const int col0 = blockIdx.x * 128;
    constexpr int NCHUNK = KDIM / 64;

    const __nv_bfloat16* srcs[4] = {
        Ah + (size_t)row0 * KDIM, Al + (size_t)row0 * KDIM,
        Bh + (size_t)col0 * KDIM, Bl + (size_t)col0 * KDIM };

    auto issue = [&](int c, int st) {
        const int k0 = c * 64;
        const uint32_t sb = smb + st * STAGE_B;
#pragma unroll
        for (int t = 0; t < 4; ++t) {
            const __nv_bfloat16* s = srcs[t];
            const uint32_t db = sb + t * TILE_B;
#pragma unroll
            for (int i = 0; i < 4; ++i) {
                int idx = i * 256 + tid;
                int row = idx >> 3, ch = idx & 7;
                cp_async16(db + row * ROWB + ch * 16,
                           s + (size_t)row * KDIM + k0 + ch * 8);
            }
        }
    };

    float acc[2][8][4];
#pragma unroll
    for (int i = 0; i < 2; i++)
#pragma unroll
        for (int j = 0; j < 8; j++)
#pragma unroll
            for (int q = 0; q < 4; q++) acc[i][j][q] = 0.f;

    const int rowA = (lane & 7) + ((lane >> 3) & 1) * 8;
    const int kA   = (lane >> 4) * 8;
    const int rowB = (lane & 7) + (lane >> 4) * 8;
    const int kB   = ((lane >> 3) & 1) * 8;

    issue(0, 0); CP_COMMIT();
    issue(1, 1); CP_COMMIT();

    for (int c = 0; c < NCHUNK; ++c) {
        CP_WAIT(1);               // this thread's stage-c copies done
        __syncthreads();          // publish stage c; all warps done reading slot (c+2)%3
        if (c + 2 < NCHUNK) issue(c + 2, (c + 2) % 3);
        CP_COMMIT();              // commit (possibly empty) keeps group count aligned

        const uint32_t sb = smb + (c % 3) * STAGE_B;
        uint32_t aBase[2], bBase[4];
#pragma unroll
        for (int mf = 0; mf < 2; ++mf)
            aBase[mf] = sb + (warp_m * 32 + mf * 16 + rowA) * ROWB + kA * 2;
#pragma unroll
        for (int nf = 0; nf < 4; ++nf)
            bBase[nf] = sb + BT_HI + (warp_n * 64 + nf * 16 + rowB) * ROWB + kB * 2;

#pragma unroll
        for (int ks = 0; ks < 4; ++ks) {
            const int kb2 = ks * 32;
            uint32_t a_hi[2][4], a_lo[2][4];
#pragma unroll
            for (int mf = 0; mf < 2; ++mf) {
                ldsm_x4(a_hi[mf], aBase[mf] + AT_HI + kb2);
                ldsm_x4(a_lo[mf], aBase[mf] + AT_LO + kb2);
            }
            uint32_t b_hi[4][4], b_lo[4][4];
#pragma unroll
            for (int nf = 0; nf < 4; ++nf) {
                ldsm_x4(b_hi[nf], bBase[nf] + kb2);
                ldsm_x4(b_lo[nf], bBase[nf] + TILE_B + kb2);
            }
#pragma unroll
            for (int mf = 0; mf < 2; ++mf)
#pragma unroll
                for (int nf = 0; nf < 8; ++nf) {
                    const uint32_t* bh = &b_hi[nf >> 1][(nf & 1) * 2];
                    mma_bf16(acc[mf][nf], a_hi[mf], bh[0], bh[1]);
                }
#pragma unroll
            for (int mf = 0; mf < 2; ++mf)
#pragma unroll
                for (int nf = 0; nf < 8; ++nf) {
                    const uint32_t* bl = &b_lo[nf >> 1][(nf & 1) * 2];
                    mma_bf16(acc[mf][nf], a_hi[mf], bl[0], bl[1]);
                }
#pragma unroll
            for (int mf = 0; mf < 2; ++mf)
#pragma unroll
                for (int nf = 0; nf < 8; ++nf) {
                    const uint32_t* bh = &b_hi[nf >> 1][(nf & 1) * 2];
                    mma_bf16(acc[mf][nf], a_lo[mf], bh[0], bh[1]);
                }
        }
    }

    // Epilogue
#pragma unroll
    for (int mf = 0; mf < 2; ++mf) {
        const int rbase = row0 + warp_m * 32 + mf * 16 + (lane >> 2);
#pragma unroll
        for (int nf = 0; nf < 8; ++nf) {
            const int col = col0 + warp_n * 64 + nf * 8 + (lane & 3) * 2;
            float2 bv = *(const float2*)&bias[col];
#pragma unroll
            for (int half = 0; half < 2; ++half) {
                const int m = rbase + half * 8;
                float wx = acc[mf][nf][half * 2 + 0] + bv.x;
                float wy = acc[mf][nf][half * 2 + 1] + bv.y;
                if (MODE == 1) {
                    float2 w = {wx, wy};
                    *(float2*)(out + (size_t)m * HID + col) = w;
                } else {
                    const int which = col0 >> 11;            // 0=q 1=k 2=v
                    const int h = (col0 & 2047) >> 7;
                    const int d = col & 127;
                    __nv_bfloat16* dh = (which == 0) ? g_qh : (which == 1) ? g_kh : g_vh;
                    __nv_bfloat16* dl = (which == 0) ? g_ql : (which == 1) ? g_kl : g_vl;
                    const int b = m >> 11, sI = m & 2047;
                    size_t off = ((size_t)(b * NHEADS + h) * SEQ + sI) * HDIM + d;
                    uint32_t lo;
                    uint32_t hi = pack_hilo(wx, wy, lo);
                    *(uint32_t*)(dh + off) = hi;
                    *(uint32_t*)(dl + off) = lo;
                }
            }
        }
    }
}

// ---------------------------------------------------------------------------
// Flash attention on HMMA (bf16x3, causal).
// Q fragments in registers; 3-stage KV cp.async pipeline, ONE sync per k-tile.
// ---------------------------------------------------------------------------
#define FROWB 272                       // 128 bf16 = 256B + 16 pad
#define FKH 0
#define FKL (64*FROWB)
#define FVH (2*64*FROWB)
#define FVL (3*64*FROWB)
#define FSTAGE_B (4*64*FROWB)           // 69632
#define FQLO_OFF (128*FROWB)            // Q-lo offset inside the Q staging slot
#define FLASH_SMEM (3*FSTAGE_B)         // 208896

__global__ __launch_bounds__(256, 1) void flash_mma_kernel()
{
    extern __shared__ char smem[];
    const uint32_t smb = smem_to_u32(smem);
    const int qt  = (int)gridDim.x - 1 - (int)blockIdx.x;   // heavy-first
    const int bh  = blockIdx.y;
    const int tid = threadIdx.x, wid = tid >> 5, lane = tid & 31;

    const size_t tb = (size_t)bh * SEQ * HDIM;
    const __nv_bfloat16 *Qh = g_qh + tb, *Ql = g_ql + tb;
    const __nv_bfloat16 *Kh = g_kh + tb, *Kl = g_kl + tb;
    const __nv_bfloat16 *Vh = g_vh + tb, *Vl = g_vl + tb;

    const int ktmax = 2 * qt + 1;
    const uint32_t slot0 = smb, slot1 = smb + FSTAGE_B, slot2 = smb + 2 * FSTAGE_B;

    auto issue_kv = [&](int kt, uint32_t sb) {
        const __nv_bfloat16* srcs[4] = {Kh, Kl, Vh, Vl};
#pragma unroll
        for (int t = 0; t < 4; ++t) {
#pragma unroll
            for (int i = 0; i < 4; ++i) {
                int idx = i * 256 + tid;
                int r = idx >> 4, ch = idx & 15;
                cp_async16(sb + t * (64 * FROWB) + r * FROWB + ch * 16,
                           srcs[t] + (size_t)(kt * 64 + r) * HDIM + ch * 8);
            }
        }
    };

    // Prologue: stage Q into slot2 (recycled as a KV stage after frag load)
#pragma unroll
    for (int i = 0; i < 8; ++i) {
        int idx = i * 256 + tid;
        int r = idx >> 4, ch = idx & 15;
        size_t g = (size_t)(qt * 128 + r) * HDIM + ch * 8;
        cp_async16(slot2 + r * FROWB + ch * 16, Qh + g);
        cp_async16(slot2 + FQLO_OFF + r * FROWB + ch * 16, Ql + g);
    }
    CP_COMMIT();
    issue_kv(0, slot0); CP_COMMIT();
    issue_kv(1, slot1); CP_COMMIT();

    CP_WAIT(2);                 // Q staged
    __syncthreads();

    // Load Q fragments to registers (held for the whole kernel)
    const uint32_t qaH = slot2 +
        (uint32_t)(wid * 16 + (lane & 7) + ((lane >> 3) & 1) * 8) * FROWB + (lane >> 4) * 16;
    const uint32_t qaL = qaH + FQLO_OFF;
    uint32_t Qfh[8][4], Qfl[8][4];
#pragma unroll
    for (int ks = 0; ks < 8; ++ks) {
        ldsm_x4(Qfh[ks], qaH + ks * 32);
        ldsm_x4(Qfl[ks], qaL + ks * 32);
    }

    const uint32_t koff = (uint32_t)((lane & 7) + (lane >> 4) * 8) * FROWB
                        + ((lane >> 3) & 1) * 16;
    const uint32_t voff = (uint32_t)((lane & 7) + ((lane >> 3) & 1) * 8) * FROWB
                        + (lane >> 4) * 16;

    float o[16][4];
#pragma unroll
    for (int i = 0; i < 16; i++)
#pragma unroll
        for (int j = 0; j < 4; j++) o[i][j] = 0.f;
    float m0 = -1e30f, m1 = -1e30f, l0 = 0.f, l1 = 0.f;
    const float scale = 0.08838834764831845f;

    const int wrow = qt * 128 + wid * 16;
    const int r0g = wrow + (lane >> 2);
    const int r1g = r0g + 8;

    for (int kt = 0; kt <= ktmax; ++kt) {
        CP_WAIT(1);              // stage kt arrived (this thread)
        __syncthreads();         // publish; all warps done with slot (kt+2)%3
        if (kt + 2 <= ktmax) {
            const uint32_t ws = ((kt + 2) % 3 == 0) ? slot0 :
                                ((kt + 2) % 3 == 1) ? slot1 : slot2;
            issue_kv(kt + 2, ws);
        }
        CP_COMMIT();

        const bool active = (kt * 64 <= wrow + 15);
        if (active) {
            const uint32_t sb = (kt % 3 == 0) ? slot0 : (kt % 3 == 1) ? slot1 : slot2;
            // ---- S = Q K^T (bf16x3) ----
            float s[8][4];
#pragma unroll
            for (int i = 0; i < 8; i++)
#pragma unroll
                for (int j = 0; j < 4; j++) s[i][j] = 0.f;
#pragma unroll
            for (int ks = 0; ks < 8; ++ks) {
                uint32_t kh[4][4], kl[4][4];
#pragma unroll
                for (int c = 0; c < 4; ++c) {
                    ldsm_x4(kh[c], sb + FKH + koff + c * (16 * FROWB) + ks * 32);
                    ldsm_x4(kl[c], sb + FKL + koff + c * (16 * FROWB) + ks * 32);
                }
#pragma unroll
                for (int c = 0; c < 4; ++c) {
                    mma_bf16(s[2*c],   Qfh[ks], kh[c][0], kh[c][1]);
                    mma_bf16(s[2*c+1], Qfh[ks], kh[c][2], kh[c][3]);
                }
#pragma unroll
                for (int c = 0; c < 4; ++c) {
                    mma_bf16(s[2*c],   Qfh[ks], kl[c][0], kl[c][1]);
                    mma_bf16(s[2*c+1], Qfh[ks], kl[c][2], kl[c][3]);
                }
#pragma unroll
                for (int c = 0; c < 4; ++c) {
                    mma_bf16(s[2*c],   Qfl[ks], kh[c][0], kh[c][1]);
                    mma_bf16(s[2*c+1], Qfl[ks], kh[c][2], kh[c][3]);
                }
            }
            // ---- scale + causal mask ----
            const bool needmask = (kt * 64 + 63 > wrow);
#pragma unroll
            for (int nf = 0; nf < 8; ++nf) {
                const int kc = kt * 64 + nf * 8 + (lane & 3) * 2;
                s[nf][0] *= scale; s[nf][1] *= scale;
                s[nf][2] *= scale; s[nf][3] *= scale;
                if (needmask) {
                    if (kc     > r0g) s[nf][0] = -1e30f;
                    if (kc + 1 > r0g) s[nf][1] = -1e30f;
                    if (kc     > r1g) s[nf][2] = -1e30f;
                    if (kc + 1 > r1g) s[nf][3] = -1e30f;
                }
            }
            // ---- online softmax ----
            float mx0 = m0, mx1 = m1;
#pragma unroll
            for (int nf = 0; nf < 8; ++nf) {
                mx0 = fmaxf(mx0, fmaxf(s[nf][0], s[nf][1]));
                mx1 = fmaxf(mx1, fmaxf(s[nf][2], s[nf][3]));
            }
            mx0 = fmaxf(mx0, __shfl_xor_sync(0xffffffffu, mx0, 1));
            mx0 = fmaxf(mx0, __shfl_xor_sync(0xffffffffu, mx0, 2));
            mx1 = fmaxf(mx1, __shfl_xor_sync(0xffffffffu, mx1, 1));
            mx1 = fmaxf(mx1, __shfl_xor_sync(0xffffffffu, mx1, 2));
            const float a0 = __expf(m0 - mx0), a1 = __expf(m1 - mx1);
            m0 = mx0; m1 = mx1;
            float sum0 = 0.f, sum1 = 0.f;
#pragma unroll
            for (int nf = 0; nf < 8; ++nf) {
                s[nf][0] = __expf(s[nf][0] - mx0);
                s[nf][1] = __expf(s[nf][1] - mx0);
                s[nf][2] = __expf(s[nf][2] - mx1);
                s[nf][3] = __expf(s[nf][3] - mx1);
                sum0 += s[nf][0] + s[nf][1];
                sum1 += s[nf][2] + s[nf][3];
            }
            sum0 += __shfl_xor_sync(0xffffffffu, sum0, 1);
            sum0 += __shfl_xor_sync(0xffffffffu, sum0, 2);
            sum1 += __shfl_xor_sync(0xffffffffu, sum1, 1);
            sum1 += __shfl_xor_sync(0xffffffffu, sum1, 2);
            l0 = l0 * a0 + sum0;
            l1 = l1 * a1 + sum1;
#pragma unroll
            for (int nf = 0; nf < 16; ++nf) {
                o[nf][0] *= a0; o[nf][1] *= a0;
                o[nf][2] *= a1; o[nf][3] *= a1;
            }
            // ---- O += P V (bf16x3) ----
#pragma unroll
            for (int ks2 = 0; ks2 < 4; ++ks2) {
                uint32_t ah[4], al[4];
                ah[0] = pack_hilo(s[2*ks2][0],   s[2*ks2][1],   al[0]);
                ah[1] = pack_hilo(s[2*ks2][2],   s[2*ks2][3],   al[1]);
                ah[2] = pack_hilo(s[2*ks2+1][0], s[2*ks2+1][1], al[2]);
                ah[3] = pack_hilo(s[2*ks2+1][2], s[2*ks2+1][3], al[3]);
#pragma unroll
                for (int dp = 0; dp < 4; ++dp) {
                    uint32_t v0h[4], v0l[4], v1h[4], v1l[4];
                    const uint32_t vb = sb + voff + ks2 * (16 * FROWB) + dp * 64;
                    ldsm_x4t(v0h, vb + FVH);
                    ldsm_x4t(v0l, vb + FVL);
                    ldsm_x4t(v1h, vb + FVH + 32);
                    ldsm_x4t(v1l, vb + FVL + 32);
                    float* o0 = o[4*dp + 0];
                    float* o1 = o[4*dp + 1];
                    float* o2 = o[4*dp + 2];
                    float* o3 = o[4*dp + 3];
                    mma_bf16(o0, ah, v0h[0], v0h[1]);
                    mma_bf16(o1, ah, v0h[2], v0h[3]);
                    mma_bf16(o2, ah, v1h[0], v1h[1]);
                    mma_bf16(o3, ah, v1h[2], v1h[3]);
                    mma_bf16(o0, ah, v0l[0], v0l[1]);
                    mma_bf16(o1, ah, v0l[2], v0l[3]);
                    mma_bf16(o2, ah, v1l[0], v1l[1]);
                    mma_bf16(o3, ah, v1l[2], v1l[3]);
                    mma_bf16(o0, al, v0h[0], v0h[1]);
                    mma_bf16(o1, al, v0h[2], v0h[3]);
                    mma_bf16(o2, al, v1h[0], v1h[1]);
                    mma_bf16(o3, al, v1h[2], v1h[3]);
                }
            }
        }
    }

    // ---- normalize + write bf16 hi/lo to g_attn [B,S,H] ----
    const float inv0 = 1.f / l0, inv1 = 1.f / l1;
    const int b = bh >> 4, hd = bh & 15;
    const size_t ob0 = ((size_t)(b * SEQ + r0g)) * HID + hd * HDIM;
    const size_t ob1 = ob0 + (size_t)8 * HID;
#pragma unroll
    for (int nf = 0; nf < 16; ++nf) {
        const int col = nf * 8 + (lane & 3) * 2;
        uint32_t lo;
        uint32_t hi = pack_hilo(o[nf][0] * inv0, o[nf][1] * inv0, lo);
        *(uint32_t*)(g_attn_hi + ob0 + col) = hi;
        *(uint32_t*)(g_attn_lo + ob0 + col) = lo;
        hi = pack_hilo(o[nf][2] * inv1, o[nf][3] * inv1, lo);
        *(uint32_t*)(g_attn_hi + ob1 + col) = hi;
        *(uint32_t*)(g_attn_lo + ob1 + col) = lo;
    }
}

// ---------------------------------------------------------------------------
extern "C" void kernel_launch(void* const* d_in, const int* in_sizes, int n_in,
                              void* d_out, int out_size)
{
    const float* hs    = (const float*)d_in[0];
    const float* W_in  = (const float*)d_in[1];
    const float* b_in  = (const float*)d_in[2];
    const float* W_out = (const float*)d_in[3];
    const float* b_out = (const float*)d_in[4];
    float* out = (float*)d_out;
    (void)in_sizes; (void)n_in; (void)out_size;

    cudaFuncSetAttribute(gemm_mma_kernel<0, HID>,
                         cudaFuncAttributeMaxDynamicSharedMemorySize, GEMM_SMEM);
    cudaFuncSetAttribute(gemm_mma_kernel<1, HID>,
                         cudaFuncAttributeMaxDynamicSharedMemorySize, GEMM_SMEM);
    cudaFuncSetAttribute(flash_mma_kernel,
                         cudaFuncAttributeMaxDynamicSharedMemorySize, FLASH_SMEM);

    __nv_bfloat16 *hs_hi, *hs_lo, *win_hi, *win_lo, *wout_hi, *wout_lo, *at_hi, *at_lo;
    cudaGetSymbolAddress((void**)&hs_hi,   g_hs_hi);
    cudaGetSymbolAddress((void**)&hs_lo,   g_hs_lo);
    cudaGetSymbolAddress((void**)&win_hi,  g_win_hi);
    cudaGetSymbolAddress((void**)&win_lo,  g_win_lo);
    cudaGetSymbolAddress((void**)&wout_hi, g_wout_hi);
    cudaGetSymbolAddress((void**)&wout_lo, g_wout_lo);
    cudaGetSymbolAddress((void**)&at_hi,   g_attn_hi);
    cudaGetSymbolAddress((void**)&at_lo,   g_attn_lo);

    // 0) fp32 -> bf16 hi/lo decompositions
    cvt_hilo_kernel<<<2048, 256>>>(hs,    hs_hi,   hs_lo,   MROWS * HID / 4);
    cvt_hilo_kernel<<<2048, 256>>>(W_in,  win_hi,  win_lo,  NQKV * HID / 4);
    cvt_hilo_kernel<<<2048, 256>>>(W_out, wout_hi, wout_lo, HID * HID / 4);

    // 1) QKV projection (HMMA bf16x3) -> q/k/v bf16 hi/lo head layout
    gemm_mma_kernel<0, HID><<<dim3(NQKV / 128, MROWS / 128), 256, GEMM_SMEM>>>(
        hs_hi, hs_lo, win_hi, win_lo, b_in, nullptr);

    // 2) causal flash attention (HMMA bf16x3) -> g_attn hi/lo [B,S,H]
    flash_mma_kernel<<<dim3(SEQ / 128, BATCH * NHEADS), 256, FLASH_SMEM>>>();

    // 3) output projection (HMMA bf16x3) -> d_out
    gemm_mma_kernel<1, HID><<<dim3(HID / 128, MROWS / 128), 256, GEMM_SMEM>>>(
        at_hi, at_lo, wout_hi, wout_lo, b_out, out);
}

// round 7
// speedup vs baseline: 3.5298x; 1.0017x over previous
#include <cuda_runtime.h>
#include <cuda_bf16.h>
#include <cstdint>

// Problem constants
#define BATCH   2
#define SEQ     2048
#define HID     2048
#define NHEADS  16
#define HDIM    128
#define MROWS   (BATCH*SEQ)      // 4096
#define NQKV    (3*HID)          // 6144

// Scratch (device globals: allocation-free) — all bf16 hi/lo pairs
__device__ __nv_bfloat16 g_qh[(size_t)BATCH*NHEADS*SEQ*HDIM], g_ql[(size_t)BATCH*NHEADS*SEQ*HDIM];
__device__ __nv_bfloat16 g_kh[(size_t)BATCH*NHEADS*SEQ*HDIM], g_kl[(size_t)BATCH*NHEADS*SEQ*HDIM];
__device__ __nv_bfloat16 g_vh[(size_t)BATCH*NHEADS*SEQ*HDIM], g_vl[(size_t)BATCH*NHEADS*SEQ*HDIM];
__device__ __nv_bfloat16 g_hs_hi[(size_t)MROWS*HID],   g_hs_lo[(size_t)MROWS*HID];
__device__ __nv_bfloat16 g_win_hi[(size_t)NQKV*HID],   g_win_lo[(size_t)NQKV*HID];
__device__ __nv_bfloat16 g_wout_hi[(size_t)HID*HID],   g_wout_lo[(size_t)HID*HID];
__device__ __nv_bfloat16 g_attn_hi[(size_t)MROWS*HID], g_attn_lo[(size_t)MROWS*HID];

__device__ __forceinline__ uint32_t smem_to_u32(const void* p) {
    uint32_t a;
    asm("{ .reg .u64 t; cvta.to.shared.u64 t, %1; cvt.u32.u64 %0, t; }"
        : "=r"(a) : "l"(p));
    return a;
}
__device__ __forceinline__ void ldsm_x4(uint32_t* r, uint32_t addr) {
    asm volatile("ldmatrix.sync.aligned.m8n8.x4.shared.b16 {%0,%1,%2,%3}, [%4];"
                 : "=r"(r[0]), "=r"(r[1]), "=r"(r[2]), "=r"(r[3]) : "r"(addr));
}
__device__ __forceinline__ void ldsm_x4t(uint32_t* r, uint32_t addr) {
    asm volatile("ldmatrix.sync.aligned.m8n8.x4.trans.shared.b16 {%0,%1,%2,%3}, [%4];"
                 : "=r"(r[0]), "=r"(r[1]), "=r"(r[2]), "=r"(r[3]) : "r"(addr));
}
__device__ __forceinline__ void mma_bf16(float* d, const uint32_t* a,
                                         uint32_t b0, uint32_t b1) {
    asm volatile("mma.sync.aligned.m16n8k16.row.col.f32.bf16.bf16.f32 "
                 "{%0,%1,%2,%3}, {%4,%5,%6,%7}, {%8,%9}, {%0,%1,%2,%3};"
                 : "+f"(d[0]), "+f"(d[1]), "+f"(d[2]), "+f"(d[3])
                 : "r"(a[0]), "r"(a[1]), "r"(a[2]), "r"(a[3]), "r"(b0), "r"(b1));
}
__device__ __forceinline__ void cp_async16(uint32_t dst, const void* src) {
    asm volatile("cp.async.cg.shared.global [%0], [%1], 16;" :: "r"(dst), "l"(src));
}
#define CP_COMMIT()  asm volatile("cp.async.commit_group;")
#define CP_WAIT(n)   asm volatile("cp.async.wait_group %0;" :: "n"(n))

// split fp32 pair -> bf16 hi pair + lo pair (packed)
__device__ __forceinline__ uint32_t pack_hilo(float x0, float x1, uint32_t& lo) {
    __nv_bfloat162 h = __float22bfloat162_rn(make_float2(x0, x1));
    float2 hf = __bfloat1622float2(h);
    __nv_bfloat162 l = __float22bfloat162_rn(make_float2(x0 - hf.x, x1 - hf.y));
    lo = *(uint32_t*)&l;
    return *(uint32_t*)&h;
}

// ---------------------------------------------------------------------------
// fp32 -> bf16 hi/lo conversion
// ---------------------------------------------------------------------------
__global__ void cvt_hilo_kernel(const float* __restrict__ src,
                                __nv_bfloat16* __restrict__ hi,
                                __nv_bfloat16* __restrict__ lo,
                                int n4)
{
    for (int i = blockIdx.x * blockDim.x + threadIdx.x; i < n4;
         i += gridDim.x * blockDim.x) {
        float4 v = ((const float4*)src)[i];
        uint2 hp, lp;
        hp.x = pack_hilo(v.x, v.y, lp.x);
        hp.y = pack_hilo(v.z, v.w, lp.y);
        ((uint2*)hi)[i] = hp;
        ((uint2*)lo)[i] = lp;
    }
}

// ---------------------------------------------------------------------------
// HMMA GEMM (bf16x3): out[m,n] = sum_k A[m,k]*W[n,k] + bias[n]
// 3-stage cp.async smem pipeline + explicit FRAGMENT double-buffer:
// k-step ks+1's LDSMs issue before ks's HMMAs -> tensor pipe stays fed
// through the shared-load phase.
// ---------------------------------------------------------------------------
#define ROWB 144
#define TILE_B (128*ROWB)
#define AT_HI 0
#define AT_LO TILE_B
#define BT_HI (2*TILE_B)
#define BT_LO (3*TILE_B)
#define STAGE_B (4*TILE_B)        // 73728
#define GEMM_SMEM (3*STAGE_B)     // 221184

template<int MODE, int KDIM>
__global__ __launch_bounds__(256, 1)
void gemm_mma_kernel(const __nv_bfloat16* __restrict__ Ah,
                     const __nv_bfloat16* __restrict__ Al,
                     const __nv_bfloat16* __restrict__ Bh,
                     const __nv_bfloat16* __restrict__ Bl,
                     const float* __restrict__ bias,
                     float* __restrict__ out)
{
    extern __shared__ char smem[];
    const uint32_t smb = smem_to_u32(smem);
    const int tid  = threadIdx.x;
    const int wid  = tid >> 5;
    const int lane = tid & 31;
    const int warp_m = wid & 3;
    const int warp_n = wid >> 2;
    const int row0 = blockIdx.y * 128;
    const int col0 = blockIdx.x * 128;
    constexpr int NCHUNK = KDIM / 64;

    const __nv_bfloat16* srcs[4] = {
        Ah + (size_t)row0 * KDIM, Al + (size_t)row0 * KDIM,
        Bh + (size_t)col0 * KDIM, Bl + (size_t)col0 * KDIM };

    auto issue = [&](int c, int st) {
        const int k0 = c * 64;
        const uint32_t sb = smb + st * STAGE_B;
#pragma unroll
        for (int t = 0; t < 4; ++t) {
            const __nv_bfloat16* s = srcs[t];
            const uint32_t db = sb + t * TILE_B;
#pragma unroll
            for (int i = 0; i < 4; ++i) {
                int idx = i * 256 + tid;
                int row = idx >> 3, ch = idx & 7;
                cp_async16(db + row * ROWB + ch * 16,
                           s + (size_t)row * KDIM + k0 + ch * 8);
            }
        }
    };

    float acc[2][8][4];
#pragma unroll
    for (int i = 0; i < 2; i++)
#pragma unroll
        for (int j = 0; j < 8; j++)
#pragma unroll
            for (int q = 0; q < 4; q++) acc[i][j][q] = 0.f;

    const int rowA = (lane & 7) + ((lane >> 3) & 1) * 8;
    const int kA   = (lane >> 4) * 8;
    const int rowB = (lane & 7) + (lane >> 4) * 8;
    const int kB   = ((lane >> 3) & 1) * 8;

    // fragment double buffers
    uint32_t fa_h[2][2][4], fa_l[2][2][4];
    uint32_t fb_h[2][4][4], fb_l[2][4][4];

    issue(0, 0); CP_COMMIT();
    issue(1, 1); CP_COMMIT();

    for (int c = 0; c < NCHUNK; ++c) {
        CP_WAIT(1);
        __syncthreads();
        if (c + 2 < NCHUNK) issue(c + 2, (c + 2) % 3);
        CP_COMMIT();

        const uint32_t sb = smb + (c % 3) * STAGE_B;
        uint32_t aBase[2], bBase[4];
#pragma unroll
        for (int mf = 0; mf < 2; ++mf)
            aBase[mf] = sb + (warp_m * 32 + mf * 16 + rowA) * ROWB + kA * 2;
#pragma unroll
        for (int nf = 0; nf < 4; ++nf)
            bBase[nf] = sb + BT_HI + (warp_n * 64 + nf * 16 + rowB) * ROWB + kB * 2;

        // prime k-step 0 fragments
#pragma unroll
        for (int mf = 0; mf < 2; ++mf) {
            ldsm_x4(fa_h[0][mf], aBase[mf] + AT_HI);
            ldsm_x4(fa_l[0][mf], aBase[mf] + AT_LO);
        }
#pragma unroll
        for (int nf = 0; nf < 4; ++nf) {
            ldsm_x4(fb_h[0][nf], bBase[nf]);
            ldsm_x4(fb_l[0][nf], bBase[nf] + TILE_B);
        }

#pragma unroll
        for (int ks = 0; ks < 4; ++ks) {
            const int cur = ks & 1, nxt = cur ^ 1;
            // issue next k-step's LDSMs FIRST (no dep on current HMMAs)
            if (ks < 3) {
                const int kb2 = (ks + 1) * 32;
#pragma unroll
                for (int mf = 0; mf < 2; ++mf) {
                    ldsm_x4(fa_h[nxt][mf], aBase[mf] + AT_HI + kb2);
                    ldsm_x4(fa_l[nxt][mf], aBase[mf] + AT_LO + kb2);
                }
#pragma unroll
                for (int nf = 0; nf < 4; ++nf) {
                    ldsm_x4(fb_h[nxt][nf], bBase[nf] + kb2);
                    ldsm_x4(fb_l[nxt][nf], bBase[nf] + TILE_B + kb2);
                }
            }
            // 3 compensation passes on current fragments
#pragma unroll
            for (int mf = 0; mf < 2; ++mf)
#pragma unroll
                for (int nf = 0; nf < 8; ++nf) {
                    const uint32_t* bh = &fb_h[cur][nf >> 1][(nf & 1) * 2];
                    mma_bf16(acc[mf][nf], fa_h[cur][mf], bh[0], bh[1]);
                }
#pragma unroll
            for (int mf = 0; mf < 2; ++mf)
#pragma unroll
                for (int nf = 0; nf < 8; ++nf) {
                    const uint32_t* bl = &fb_l[cur][nf >> 1][(nf & 1) * 2];
                    mma_bf16(acc[mf][nf], fa_h[cur][mf], bl[0], bl[1]);
                }
#pragma unroll
            for (int mf = 0; mf < 2; ++mf)
#pragma unroll
                for (int nf = 0; nf < 8; ++nf) {
                    const uint32_t* bh = &fb_h[cur][nf >> 1][(nf & 1) * 2];
                    mma_bf16(acc[mf][nf], fa_l[cur][mf], bh[0], bh[1]);
                }
        }
    }

    // Epilogue
#pragma unroll
    for (int mf = 0; mf < 2; ++mf) {
        const int rbase = row0 + warp_m * 32 + mf * 16 + (lane >> 2);
#pragma unroll
        for (int nf = 0; nf < 8; ++nf) {
            const int col = col0 + warp_n * 64 + nf * 8 + (lane & 3) * 2;
            float2 bv = *(const float2*)&bias[col];
#pragma unroll
            for (int half = 0; half < 2; ++half) {
                const int m = rbase + half * 8;
                float wx = acc[mf][nf][half * 2 + 0] + bv.x;
                float wy = acc[mf][nf][half * 2 + 1] + bv.y;
                if (MODE == 1) {
                    float2 w = {wx, wy};
                    *(float2*)(out + (size_t)m * HID + col) = w;
                } else {
                    const int which = col0 >> 11;            // 0=q 1=k 2=v
                    const int h = (col0 & 2047) >> 7;
                    const int d = col & 127;
                    __nv_bfloat16* dh = (which == 0) ? g_qh : (which == 1) ? g_kh : g_vh;
                    __nv_bfloat16* dl = (which == 0) ? g_ql : (which == 1) ? g_kl : g_vl;
                    const int b = m >> 11, sI = m & 2047;
                    size_t off = ((size_t)(b * NHEADS + h) * SEQ + sI) * HDIM + d;
                    uint32_t lo;
                    uint32_t hi = pack_hilo(wx, wy, lo);
                    *(uint32_t*)(dh + off) = hi;
                    *(uint32_t*)(dl + off) = lo;
                }
            }
        }
    }
}

// ---------------------------------------------------------------------------
// Flash attention on HMMA (bf16x3, causal) — unchanged from R6.
// ---------------------------------------------------------------------------
#define FROWB 272
#define FKH 0
#define FKL (64*FROWB)
#define FVH (2*64*FROWB)
#define FVL (3*64*FROWB)
#define FSTAGE_B (4*64*FROWB)           // 69632
#define FQLO_OFF (128*FROWB)
#define FLASH_SMEM (3*FSTAGE_B)         // 208896

__global__ __launch_bounds__(256, 1) void flash_mma_kernel()
{
    extern __shared__ char smem[];
    const uint32_t smb = smem_to_u32(smem);
    const int qt  = (int)gridDim.x - 1 - (int)blockIdx.x;
    const int bh  = blockIdx.y;
    const int tid = threadIdx.x, wid = tid >> 5, lane = tid & 31;

    const size_t tb = (size_t)bh * SEQ * HDIM;
    const __nv_bfloat16 *Qh = g_qh + tb, *Ql = g_ql + tb;
    const __nv_bfloat16 *Kh = g_kh + tb, *Kl = g_kl + tb;
    const __nv_bfloat16 *Vh = g_vh + tb, *Vl = g_vl + tb;

    const int ktmax = 2 * qt + 1;
    const uint32_t slot0 = smb, slot1 = smb + FSTAGE_B, slot2 = smb + 2 * FSTAGE_B;

    auto issue_kv = [&](int kt, uint32_t sb) {
        const __nv_bfloat16* srcs[4] = {Kh, Kl, Vh, Vl};
#pragma unroll
        for (int t = 0; t < 4; ++t) {
#pragma unroll
            for (int i = 0; i < 4; ++i) {
                int idx = i * 256 + tid;
                int r = idx >> 4, ch = idx & 15;
                cp_async16(sb + t * (64 * FROWB) + r * FROWB + ch * 16,
                           srcs[t] + (size_t)(kt * 64 + r) * HDIM + ch * 8);
            }
        }
    };

#pragma unroll
    for (int i = 0; i < 8; ++i) {
        int idx = i * 256 + tid;
        int r = idx >> 4, ch = idx & 15;
        size_t g = (size_t)(qt * 128 + r) * HDIM + ch * 8;
        cp_async16(slot2 + r * FROWB + ch * 16, Qh + g);
        cp_async16(slot2 + FQLO_OFF + r * FROWB + ch * 16, Ql + g);
    }
    CP_COMMIT();
    issue_kv(0, slot0); CP_COMMIT();
    issue_kv(1, slot1); CP_COMMIT();

    CP_WAIT(2);
    __syncthreads();

    const uint32_t qaH = slot2 +
        (uint32_t)(wid * 16 + (lane & 7) + ((lane >> 3) & 1) * 8) * FROWB + (lane >> 4) * 16;
    const uint32_t qaL = qaH + FQLO_OFF;
    uint32_t Qfh[8][4], Qfl[8][4];
#pragma unroll
    for (int ks = 0; ks < 8; ++ks) {
        ldsm_x4(Qfh[ks], qaH + ks * 32);
        ldsm_x4(Qfl[ks], qaL + ks * 32);
    }

    const uint32_t koff = (uint32_t)((lane & 7) + (lane >> 4) * 8) * FROWB
                        + ((lane >> 3) & 1) * 16;
    const uint32_t voff = (uint32_t)((lane & 7) + ((lane >> 3) & 1) * 8) * FROWB
                        + (lane >> 4) * 16;

    float o[16][4];
#pragma unroll
    for (int i = 0; i < 16; i++)
#pragma unroll
        for (int j = 0; j < 4; j++) o[i][j] = 0.f;
    float m0 = -1e30f, m1 = -1e30f, l0 = 0.f, l1 = 0.f;
    const float scale = 0.08838834764831845f;

    const int wrow = qt * 128 + wid * 16;
    const int r0g = wrow + (lane >> 2);
    const int r1g = r0g + 8;

    for (int kt = 0; kt <= ktmax; ++kt) {
        CP_WAIT(1);
        __syncthreads();
        if (kt + 2 <= ktmax) {
            const uint32_t ws = ((kt + 2) % 3 == 0) ? slot0 :
                                ((kt + 2) % 3 == 1) ? slot1 : slot2;
            issue_kv(kt + 2, ws);
        }
        CP_COMMIT();

        const bool active = (kt * 64 <= wrow + 15);
        if (active) {
            const uint32_t sb = (kt % 3 == 0) ? slot0 : (kt % 3 == 1) ? slot1 : slot2;
            float s[8][4];
#pragma unroll
            for (int i = 0; i < 8; i++)
#pragma unroll
                for (int j = 0; j < 4; j++) s[i][j] = 0.f;
#pragma unroll
            for (int ks = 0; ks < 8; ++ks) {
                uint32_t kh[4][4], kl[4][4];
#pragma unroll
                for (int c = 0; c < 4; ++c) {
                    ldsm_x4(kh[c], sb + FKH + koff + c * (16 * FROWB) + ks * 32);
                    ldsm_x4(kl[c], sb + FKL + koff + c * (16 * FROWB) + ks * 32);
                }
#pragma unroll
                for (int c = 0; c < 4; ++c) {
                    mma_bf16(s[2*c],   Qfh[ks], kh[c][0], kh[c][1]);
                    mma_bf16(s[2*c+1], Qfh[ks], kh[c][2], kh[c][3]);
                }
#pragma unroll
                for (int c = 0; c < 4; ++c) {
                    mma_bf16(s[2*c],   Qfh[ks], kl[c][0], kl[c][1]);
                    mma_bf16(s[2*c+1], Qfh[ks], kl[c][2], kl[c][3]);
                }
#pragma unroll
                for (int c = 0; c < 4; ++c) {
                    mma_bf16(s[2*c],   Qfl[ks], kh[c][0], kh[c][1]);
                    mma_bf16(s[2*c+1], Qfl[ks], kh[c][2], kh[c][3]);
                }
            }
            const bool needmask = (kt * 64 + 63 > wrow);
#pragma unroll
            for (int nf = 0; nf < 8; ++nf) {
                const int kc = kt * 64 + nf * 8 + (lane & 3) * 2;
                s[nf][0] *= scale; s[nf][1] *= scale;
                s[nf][2] *= scale; s[nf][3] *= scale;
                if (needmask) {
                    if (kc     > r0g) s[nf][0] = -1e30f;
                    if (kc + 1 > r0g) s[nf][1] = -1e30f;
                    if (kc     > r1g) s[nf][2] = -1e30f;
                    if (kc + 1 > r1g) s[nf][3] = -1e30f;
                }
            }
            float mx0 = m0, mx1 = m1;
#pragma unroll
            for (int nf = 0; nf < 8; ++nf) {
                mx0 = fmaxf(mx0, fmaxf(s[nf][0], s[nf][1]));
                mx1 = fmaxf(mx1, fmaxf(s[nf][2], s[nf][3]));
            }
            mx0 = fmaxf(mx0, __shfl_xor_sync(0xffffffffu, mx0, 1));
            mx0 = fmaxf(mx0, __shfl_xor_sync(0xffffffffu, mx0, 2));
            mx1 = fmaxf(mx1, __shfl_xor_sync(0xffffffffu, mx1, 1));
            mx1 = fmaxf(mx1, __shfl_xor_sync(0xffffffffu, mx1, 2));
            const float a0 = __expf(m0 - mx0), a1 = __expf(m1 - mx1);
            m0 = mx0; m1 = mx1;
            float sum0 = 0.f, sum1 = 0.f;
#pragma unroll
            for (int nf = 0; nf < 8; ++nf) {
                s[nf][0] = __expf(s[nf][0] - mx0);
                s[nf][1] = __expf(s[nf][1] - mx0);
                s[nf][2] = __expf(s[nf][2] - mx1);
                s[nf][3] = __expf(s[nf][3] - mx1);
                sum0 += s[nf][0] + s[nf][1];
                sum1 += s[nf][2] + s[nf][3];
            }
            sum0 += __shfl_xor_sync(0xffffffffu, sum0, 1);
            sum0 += __shfl_xor_sync(0xffffffffu, sum0, 2);
            sum1 += __shfl_xor_sync(0xffffffffu, sum1, 1);
            sum1 += __shfl_xor_sync(0xffffffffu, sum1, 2);
            l0 = l0 * a0 + sum0;
            l1 = l1 * a1 + sum1;
#pragma unroll
            for (int nf = 0; nf < 16; ++nf) {
                o[nf][0] *= a0; o[nf][1] *= a0;
                o[nf][2] *= a1; o[nf][3] *= a1;
            }
#pragma unroll
            for (int ks2 = 0; ks2 < 4; ++ks2) {
                uint32_t ah[4], al[4];
                ah[0] = pack_hilo(s[2*ks2][0],   s[2*ks2][1],   al[0]);
                ah[1] = pack_hilo(s[2*ks2][2],   s[2*ks2][3],   al[1]);
                ah[2] = pack_hilo(s[2*ks2+1][0], s[2*ks2+1][1], al[2]);
                ah[3] = pack_hilo(s[2*ks2+1][2], s[2*ks2+1][3], al[3]);
#pragma unroll
                for (int dp = 0; dp < 4; ++dp) {
                    uint32_t v0h[4], v0l[4], v1h[4], v1l[4];
                    const uint32_t vb = sb + voff + ks2 * (16 * FROWB) + dp * 64;
                    ldsm_x4t(v0h, vb + FVH);
                    ldsm_x4t(v0l, vb + FVL);
                    ldsm_x4t(v1h, vb + FVH + 32);
                    ldsm_x4t(v1l, vb + FVL + 32);
                    float* o0 = o[4*dp + 0];
                    float* o1 = o[4*dp + 1];
                    float* o2 = o[4*dp + 2];
                    float* o3 = o[4*dp + 3];
                    mma_bf16(o0, ah, v0h[0], v0h[1]);
                    mma_bf16(o1, ah, v0h[2], v0h[3]);
                    mma_bf16(o2, ah, v1h[0], v1h[1]);
                    mma_bf16(o3, ah, v1h[2], v1h[3]);
                    mma_bf16(o0, ah, v0l[0], v0l[1]);
                    mma_bf16(o1, ah, v0l[2], v0l[3]);
                    mma_bf16(o2, ah, v1l[0], v1l[1]);
                    mma_bf16(o3, ah, v1l[2], v1l[3]);
                    mma_bf16(o0, al, v0h[0], v0h[1]);
                    mma_bf16(o1, al, v0h[2], v0h[3]);
                    mma_bf16(o2, al, v1h[0], v1h[1]);
                    mma_bf16(o3, al, v1h[2], v1h[3]);
                }
            }
        }
    }

    const float inv0 = 1.f / l0, inv1 = 1.f / l1;
    const int b = bh >> 4, hd = bh & 15;
    const size_t ob0 = ((size_t)(b * SEQ + r0g)) * HID + hd * HDIM;
    const size_t ob1 = ob0 + (size_t)8 * HID;
#pragma unroll
    for (int nf = 0; nf < 16; ++nf) {
        const int col = nf * 8 + (lane & 3) * 2;
        uint32_t lo;
        uint32_t hi = pack_hilo(o[nf][0] * inv0, o[nf][1] * inv0, lo);
        *(uint32_t*)(g_attn_hi + ob0 + col) = hi;
        *(uint32_t*)(g_attn_lo + ob0 + col) = lo;
        hi = pack_hilo(o[nf][2] * inv1, o[nf][3] * inv1, lo);
        *(uint32_t*)(g_attn_hi + ob1 + col) = hi;
        *(uint32_t*)(g_attn_lo + ob1 + col) = lo;
    }
}

// ---------------------------------------------------------------------------
extern "C" void kernel_launch(void* const* d_in, const int* in_sizes, int n_in,
                              void* d_out, int out_size)
{
    const float* hs    = (const float*)d_in[0];
    const float* W_in  = (const float*)d_in[1];
    const float* b_in  = (const float*)d_in[2];
    const float* W_out = (const float*)d_in[3];
    const float* b_out = (const float*)d_in[4];
    float* out = (float*)d_out;
    (void)in_sizes; (void)n_in; (void)out_size;

    cudaFuncSetAttribute(gemm_mma_kernel<0, HID>,
                         cudaFuncAttributeMaxDynamicSharedMemorySize, GEMM_SMEM);
    cudaFuncSetAttribute(gemm_mma_kernel<1, HID>,
                         cudaFuncAttributeMaxDynamicSharedMemorySize, GEMM_SMEM);
    cudaFuncSetAttribute(flash_mma_kernel,
                         cudaFuncAttributeMaxDynamicSharedMemorySize, FLASH_SMEM);

    __nv_bfloat16 *hs_hi, *hs_lo, *win_hi, *win_lo, *wout_hi, *wout_lo, *at_hi, *at_lo;
    cudaGetSymbolAddress((void**)&hs_hi,   g_hs_hi);
    cudaGetSymbolAddress((void**)&hs_lo,   g_hs_lo);
    cudaGetSymbolAddress((void**)&win_hi,  g_win_hi);
    cudaGetSymbolAddress((void**)&win_lo,  g_win_lo);
    cudaGetSymbolAddress((void**)&wout_hi, g_wout_hi);
    cudaGetSymbolAddress((void**)&wout_lo, g_wout_lo);
    cudaGetSymbolAddress((void**)&at_hi,   g_attn_hi);
    cudaGetSymbolAddress((void**)&at_lo,   g_attn_lo);

    cvt_hilo_kernel<<<2048, 256>>>(hs,    hs_hi,   hs_lo,   MROWS * HID / 4);
    cvt_hilo_kernel<<<2048, 256>>>(W_in,  win_hi,  win_lo,  NQKV * HID / 4);
    cvt_hilo_kernel<<<2048, 256>>>(W_out, wout_hi, wout_lo, HID * HID / 4);

    gemm_mma_kernel<0, HID><<<dim3(NQKV / 128, MROWS / 128), 256, GEMM_SMEM>>>(
        hs_hi, hs_lo, win_hi, win_lo, b_in, nullptr);

    flash_mma_kernel<<<dim3(SEQ / 128, BATCH * NHEADS), 256, FLASH_SMEM>>>();

    gemm_mma_kernel<1, HID><<<dim3(HID / 128, MROWS / 128), 256, GEMM_SMEM>>>(
        at_hi, at_lo, wout_hi, wout_lo, b_out, out);
}

// round 8
// speedup vs baseline: 3.7064x; 1.0500x over previous
#include <cuda_runtime.h>
#include <cuda_bf16.h>
#include <cstdint>

// Problem constants
#define BATCH   2
#define SEQ     2048
#define HID     2048
#define NHEADS  16
#define HDIM    128
#define MROWS   (BATCH*SEQ)      // 4096
#define NQKV    (3*HID)          // 6144

// Scratch (device globals: allocation-free) — all bf16 hi/lo pairs
__device__ __nv_bfloat16 g_qh[(size_t)BATCH*NHEADS*SEQ*HDIM], g_ql[(size_t)BATCH*NHEADS*SEQ*HDIM];
__device__ __nv_bfloat16 g_kh[(size_t)BATCH*NHEADS*SEQ*HDIM], g_kl[(size_t)BATCH*NHEADS*SEQ*HDIM];
__device__ __nv_bfloat16 g_vh[(size_t)BATCH*NHEADS*SEQ*HDIM], g_vl[(size_t)BATCH*NHEADS*SEQ*HDIM];
__device__ __nv_bfloat16 g_hs_hi[(size_t)MROWS*HID],   g_hs_lo[(size_t)MROWS*HID];
__device__ __nv_bfloat16 g_win_hi[(size_t)NQKV*HID],   g_win_lo[(size_t)NQKV*HID];
__device__ __nv_bfloat16 g_wout_hi[(size_t)HID*HID],   g_wout_lo[(size_t)HID*HID];
__device__ __nv_bfloat16 g_attn_hi[(size_t)MROWS*HID], g_attn_lo[(size_t)MROWS*HID];

__device__ __forceinline__ uint32_t smem_to_u32(const void* p) {
    uint32_t a;
    asm("{ .reg .u64 t; cvta.to.shared.u64 t, %1; cvt.u32.u64 %0, t; }"
        : "=r"(a) : "l"(p));
    return a;
}
__device__ __forceinline__ void ldsm_x4(uint32_t* r, uint32_t addr) {
    asm volatile("ldmatrix.sync.aligned.m8n8.x4.shared.b16 {%0,%1,%2,%3}, [%4];"
                 : "=r"(r[0]), "=r"(r[1]), "=r"(r[2]), "=r"(r[3]) : "r"(addr));
}
__device__ __forceinline__ void ldsm_x4t(uint32_t* r, uint32_t addr) {
    asm volatile("ldmatrix.sync.aligned.m8n8.x4.trans.shared.b16 {%0,%1,%2,%3}, [%4];"
                 : "=r"(r[0]), "=r"(r[1]), "=r"(r[2]), "=r"(r[3]) : "r"(addr));
}
__device__ __forceinline__ void mma_bf16(float* d, const uint32_t* a,
                                         uint32_t b0, uint32_t b1) {
    asm volatile("mma.sync.aligned.m16n8k16.row.col.f32.bf16.bf16.f32 "
                 "{%0,%1,%2,%3}, {%4,%5,%6,%7}, {%8,%9}, {%0,%1,%2,%3};"
                 : "+f"(d[0]), "+f"(d[1]), "+f"(d[2]), "+f"(d[3])
                 : "r"(a[0]), "r"(a[1]), "r"(a[2]), "r"(a[3]), "r"(b0), "r"(b1));
}
__device__ __forceinline__ void cp_async16(uint32_t dst, const void* src) {
    asm volatile("cp.async.cg.shared.global [%0], [%1], 16;" :: "r"(dst), "l"(src));
}
#define CP_COMMIT()  asm volatile("cp.async.commit_group;")
#define CP_WAIT(n)   asm volatile("cp.async.wait_group %0;" :: "n"(n))

// split fp32 pair -> bf16 hi pair + lo pair (packed)
__device__ __forceinline__ uint32_t pack_hilo(float x0, float x1, uint32_t& lo) {
    __nv_bfloat162 h = __float22bfloat162_rn(make_float2(x0, x1));
    float2 hf = __bfloat1622float2(h);
    __nv_bfloat162 l = __float22bfloat162_rn(make_float2(x0 - hf.x, x1 - hf.y));
    lo = *(uint32_t*)&l;
    return *(uint32_t*)&h;
}

// ---------------------------------------------------------------------------
// fp32 -> bf16 hi/lo conversion
// ---------------------------------------------------------------------------
__global__ void cvt_hilo_kernel(const float* __restrict__ src,
                                __nv_bfloat16* __restrict__ hi,
                                __nv_bfloat16* __restrict__ lo,
                                int n4)
{
    for (int i = blockIdx.x * blockDim.x + threadIdx.x; i < n4;
         i += gridDim.x * blockDim.x) {
        float4 v = ((const float4*)src)[i];
        uint2 hp, lp;
        hp.x = pack_hilo(v.x, v.y, lp.x);
        hp.y = pack_hilo(v.z, v.w, lp.y);
        ((uint2*)hi)[i] = hp;
        ((uint2*)lo)[i] = lp;
    }
}

// ---------------------------------------------------------------------------
// HMMA GEMM (bf16x3): out[m,n] = sum_k A[m,k]*W[n,k] + bias[n]
// 512 threads (16 warps = 4/SMSP), block tile 128x256, warp tile 32x64,
// 2-stage cp.async pipeline, one __syncthreads per K-chunk.
// ---------------------------------------------------------------------------
#define ROWB 144
#define A_TILE_B (128*ROWB)       // 18432
#define B_TILE_B (256*ROWB)       // 36864
#define AT_HI 0
#define AT_LO A_TILE_B
#define BT_HI (2*A_TILE_B)
#define BT_LO (2*A_TILE_B + B_TILE_B)
#define STAGE_B (2*A_TILE_B + 2*B_TILE_B)   // 110592
#define GEMM_SMEM (2*STAGE_B)               // 221184

template<int MODE, int KDIM>
__global__ __launch_bounds__(512, 1)
void gemm_mma_kernel(const __nv_bfloat16* __restrict__ Ah,
                     const __nv_bfloat16* __restrict__ Al,
                     const __nv_bfloat16* __restrict__ Bh,
                     const __nv_bfloat16* __restrict__ Bl,
                     const float* __restrict__ bias,
                     float* __restrict__ out)
{
    extern __shared__ char smem[];
    const uint32_t smb = smem_to_u32(smem);
    const int tid  = threadIdx.x;
    const int wid  = tid >> 5;
    const int lane = tid & 31;
    const int warp_m = wid & 3;       // 4 warps over M (32 rows each)
    const int warp_n = wid >> 2;      // 4 warps over N (64 cols each)
    const int row0 = blockIdx.y * 128;
    const int col0 = blockIdx.x * 256;
    constexpr int NCHUNK = KDIM / 64;

    const __nv_bfloat16* srcA[2] = { Ah + (size_t)row0 * KDIM, Al + (size_t)row0 * KDIM };
    const __nv_bfloat16* srcB[2] = { Bh + (size_t)col0 * KDIM, Bl + (size_t)col0 * KDIM };

    auto issue = [&](int c, int st) {
        const int k0 = c * 64;
        const uint32_t sb = smb + st * STAGE_B;
#pragma unroll
        for (int t = 0; t < 2; ++t) {            // A hi/lo: 128 rows
            const __nv_bfloat16* s = srcA[t];
            const uint32_t db = sb + AT_HI + t * A_TILE_B;
#pragma unroll
            for (int i = 0; i < 2; ++i) {
                int idx = i * 512 + tid;         // 0..1023
                int row = idx >> 3, ch = idx & 7;
                cp_async16(db + row * ROWB + ch * 16,
                           s + (size_t)row * KDIM + k0 + ch * 8);
            }
        }
#pragma unroll
        for (int t = 0; t < 2; ++t) {            // B hi/lo: 256 rows
            const __nv_bfloat16* s = srcB[t];
            const uint32_t db = sb + BT_HI + t * B_TILE_B;
#pragma unroll
            for (int i = 0; i < 4; ++i) {
                int idx = i * 512 + tid;         // 0..2047
                int row = idx >> 3, ch = idx & 7;
                cp_async16(db + row * ROWB + ch * 16,
                           s + (size_t)row * KDIM + k0 + ch * 8);
            }
        }
    };

    float acc[2][8][4];
#pragma unroll
    for (int i = 0; i < 2; i++)
#pragma unroll
        for (int j = 0; j < 8; j++)
#pragma unroll
            for (int q = 0; q < 4; q++) acc[i][j][q] = 0.f;

    const int rowA = (lane & 7) + ((lane >> 3) & 1) * 8;
    const int kA   = (lane >> 4) * 8;
    const int rowB = (lane & 7) + (lane >> 4) * 8;
    const int kB   = ((lane >> 3) & 1) * 8;

    issue(0, 0); CP_COMMIT();

    for (int c = 0; c < NCHUNK; ++c) {
        CP_WAIT(0);               // own copies of stage c complete
        __syncthreads();          // stage c visible to all; all done computing c-1
        if (c + 1 < NCHUNK) { issue(c + 1, (c + 1) & 1); CP_COMMIT(); }

        const uint32_t sb = smb + (c & 1) * STAGE_B;
        uint32_t aBase[2], bBase[4];
#pragma unroll
        for (int mf = 0; mf < 2; ++mf)
            aBase[mf] = sb + (warp_m * 32 + mf * 16 + rowA) * ROWB + kA * 2;
#pragma unroll
        for (int nf = 0; nf < 4; ++nf)
            bBase[nf] = sb + BT_HI + (warp_n * 64 + nf * 16 + rowB) * ROWB + kB * 2;

#pragma unroll
        for (int ks = 0; ks < 4; ++ks) {
            const int kb2 = ks * 32;
            uint32_t a_hi[2][4], a_lo[2][4];
#pragma unroll
            for (int mf = 0; mf < 2; ++mf) {
                ldsm_x4(a_hi[mf], aBase[mf] + AT_HI + kb2);
                ldsm_x4(a_lo[mf], aBase[mf] + (AT_LO - AT_HI) + kb2);
            }
            // B processed in two halves to cap live registers
#pragma unroll
            for (int h = 0; h < 2; ++h) {
                uint32_t b_hi[2][4], b_lo[2][4];
#pragma unroll
                for (int j = 0; j < 2; ++j) {
                    ldsm_x4(b_hi[j], bBase[h * 2 + j] + kb2);
                    ldsm_x4(b_lo[j], bBase[h * 2 + j] + B_TILE_B + kb2);
                }
                // pass 1: Ahi*Bhi (8 independent accs)
#pragma unroll
                for (int mf = 0; mf < 2; ++mf)
#pragma unroll
                    for (int j = 0; j < 4; ++j) {
                        const uint32_t* bh = &b_hi[j >> 1][(j & 1) * 2];
                        mma_bf16(acc[mf][h * 4 + j], a_hi[mf], bh[0], bh[1]);
                    }
                // pass 2: Ahi*Blo
#pragma unroll
                for (int mf = 0; mf < 2; ++mf)
#pragma unroll
                    for (int j = 0; j < 4; ++j) {
                        const uint32_t* bl = &b_lo[j >> 1][(j & 1) * 2];
                        mma_bf16(acc[mf][h * 4 + j], a_hi[mf], bl[0], bl[1]);
                    }
                // pass 3: Alo*Bhi
#pragma unroll
                for (int mf = 0; mf < 2; ++mf)
#pragma unroll
                    for (int j = 0; j < 4; ++j) {
                        const uint32_t* bh = &b_hi[j >> 1][(j & 1) * 2];
                        mma_bf16(acc[mf][h * 4 + j], a_lo[mf], bh[0], bh[1]);
                    }
            }
        }
    }

    // Epilogue
#pragma unroll
    for (int mf = 0; mf < 2; ++mf) {
        const int rbase = row0 + warp_m * 32 + mf * 16 + (lane >> 2);
#pragma unroll
        for (int nf = 0; nf < 8; ++nf) {
            const int col = col0 + warp_n * 64 + nf * 8 + (lane & 3) * 2;
            float2 bv = *(const float2*)&bias[col];
#pragma unroll
            for (int half = 0; half < 2; ++half) {
                const int m = rbase + half * 8;
                float wx = acc[mf][nf][half * 2 + 0] + bv.x;
                float wy = acc[mf][nf][half * 2 + 1] + bv.y;
                if (MODE == 1) {
                    float2 w = {wx, wy};
                    *(float2*)(out + (size_t)m * HID + col) = w;
                } else {
                    const int which = col >> 11;             // 0=q 1=k 2=v
                    const int h2 = (col & 2047) >> 7;
                    const int d = col & 127;
                    __nv_bfloat16* dh = (which == 0) ? g_qh : (which == 1) ? g_kh : g_vh;
                    __nv_bfloat16* dl = (which == 0) ? g_ql : (which == 1) ? g_kl : g_vl;
                    const int b = m >> 11, sI = m & 2047;
                    size_t off = ((size_t)(b * NHEADS + h2) * SEQ + sI) * HDIM + d;
                    uint32_t lo;
                    uint32_t hi = pack_hilo(wx, wy, lo);
                    *(uint32_t*)(dh + off) = hi;
                    *(uint32_t*)(dl + off) = lo;
                }
            }
        }
    }
}

// ---------------------------------------------------------------------------
// Flash attention on HMMA (bf16x3, causal) — unchanged from R7.
// ---------------------------------------------------------------------------
#define FROWB 272
#define FKH 0
#define FKL (64*FROWB)
#define FVH (2*64*FROWB)
#define FVL (3*64*FROWB)
#define FSTAGE_B (4*64*FROWB)           // 69632
#define FQLO_OFF (128*FROWB)
#define FLASH_SMEM (3*FSTAGE_B)         // 208896

__global__ __launch_bounds__(256, 1) void flash_mma_kernel()
{
    extern __shared__ char smem[];
    const uint32_t smb = smem_to_u32(smem);
    const int qt  = (int)gridDim.x - 1 - (int)blockIdx.x;
    const int bh  = blockIdx.y;
    const int tid = threadIdx.x, wid = tid >> 5, lane = tid & 31;

    const size_t tb = (size_t)bh * SEQ * HDIM;
    const __nv_bfloat16 *Qh = g_qh + tb, *Ql = g_ql + tb;
    const __nv_bfloat16 *Kh = g_kh + tb, *Kl = g_kl + tb;
    const __nv_bfloat16 *Vh = g_vh + tb, *Vl = g_vl + tb;

    const int ktmax = 2 * qt + 1;
    const uint32_t slot0 = smb, slot1 = smb + FSTAGE_B, slot2 = smb + 2 * FSTAGE_B;

    auto issue_kv = [&](int kt, uint32_t sb) {
        const __nv_bfloat16* srcs[4] = {Kh, Kl, Vh, Vl};
#pragma unroll
        for (int t = 0; t < 4; ++t) {
#pragma unroll
            for (int i = 0; i < 4; ++i) {
                int idx = i * 256 + tid;
                int r = idx >> 4, ch = idx & 15;
                cp_async16(sb + t * (64 * FROWB) + r * FROWB + ch * 16,
                           srcs[t] + (size_t)(kt * 64 + r) * HDIM + ch * 8);
            }
        }
    };

#pragma unroll
    for (int i = 0; i < 8; ++i) {
        int idx = i * 256 + tid;
        int r = idx >> 4, ch = idx & 15;
        size_t g = (size_t)(qt * 128 + r) * HDIM + ch * 8;
        cp_async16(slot2 + r * FROWB + ch * 16, Qh + g);
        cp_async16(slot2 + FQLO_OFF + r * FROWB + ch * 16, Ql + g);
    }
    CP_COMMIT();
    issue_kv(0, slot0); CP_COMMIT();
    issue_kv(1, slot1); CP_COMMIT();

    CP_WAIT(2);
    __syncthreads();

    const uint32_t qaH = slot2 +
        (uint32_t)(wid * 16 + (lane & 7) + ((lane >> 3) & 1) * 8) * FROWB + (lane >> 4) * 16;
    const uint32_t qaL = qaH + FQLO_OFF;
    uint32_t Qfh[8][4], Qfl[8][4];
#pragma unroll
    for (int ks = 0; ks < 8; ++ks) {
        ldsm_x4(Qfh[ks], qaH + ks * 32);
        ldsm_x4(Qfl[ks], qaL + ks * 32);
    }

    const uint32_t koff = (uint32_t)((lane & 7) + (lane >> 4) * 8) * FROWB
                        + ((lane >> 3) & 1) * 16;
    const uint32_t voff = (uint32_t)((lane & 7) + ((lane >> 3) & 1) * 8) * FROWB
                        + (lane >> 4) * 16;

    float o[16][4];
#pragma unroll
    for (int i = 0; i < 16; i++)
#pragma unroll
        for (int j = 0; j < 4; j++) o[i][j] = 0.f;
    float m0 = -1e30f, m1 = -1e30f, l0 = 0.f, l1 = 0.f;
    const float scale = 0.08838834764831845f;

    const int wrow = qt * 128 + wid * 16;
    const int r0g = wrow + (lane >> 2);
    const int r1g = r0g + 8;

    for (int kt = 0; kt <= ktmax; ++kt) {
        CP_WAIT(1);
        __syncthreads();
        if (kt + 2 <= ktmax) {
            const uint32_t ws = ((kt + 2) % 3 == 0) ? slot0 :
                                ((kt + 2) % 3 == 1) ? slot1 : slot2;
            issue_kv(kt + 2, ws);
        }
        CP_COMMIT();

        const bool active = (kt * 64 <= wrow + 15);
        if (active) {
            const uint32_t sb = (kt % 3 == 0) ? slot0 : (kt % 3 == 1) ? slot1 : slot2;
            float s[8][4];
#pragma unroll
            for (int i = 0; i < 8; i++)
#pragma unroll
                for (int j = 0; j < 4; j++) s[i][j] = 0.f;
#pragma unroll
            for (int ks = 0; ks < 8; ++ks) {
                uint32_t kh[4][4], kl[4][4];
#pragma unroll
                for (int c = 0; c < 4; ++c) {
                    ldsm_x4(kh[c], sb + FKH + koff + c * (16 * FROWB) + ks * 32);
                    ldsm_x4(kl[c], sb + FKL + koff + c * (16 * FROWB) + ks * 32);
                }
#pragma unroll
                for (int c = 0; c < 4; ++c) {
                    mma_bf16(s[2*c],   Qfh[ks], kh[c][0], kh[c][1]);
                    mma_bf16(s[2*c+1], Qfh[ks], kh[c][2], kh[c][3]);
                }
#pragma unroll
                for (int c = 0; c < 4; ++c) {
                    mma_bf16(s[2*c],   Qfh[ks], kl[c][0], kl[c][1]);
                    mma_bf16(s[2*c+1], Qfh[ks], kl[c][2], kl[c][3]);
                }
#pragma unroll
                for (int c = 0; c < 4; ++c) {
                    mma_bf16(s[2*c],   Qfl[ks], kh[c][0], kh[c][1]);
                    mma_bf16(s[2*c+1], Qfl[ks], kh[c][2], kh[c][3]);
                }
            }
            const bool needmask = (kt * 64 + 63 > wrow);
#pragma unroll
            for (int nf = 0; nf < 8; ++nf) {
                const int kc = kt * 64 + nf * 8 + (lane & 3) * 2;
                s[nf][0] *= scale; s[nf][1] *= scale;
                s[nf][2] *= scale; s[nf][3] *= scale;
                if (needmask) {
                    if (kc     > r0g) s[nf][0] = -1e30f;
                    if (kc + 1 > r0g) s[nf][1] = -1e30f;
                    if (kc     > r1g) s[nf][2] = -1e30f;
                    if (kc + 1 > r1g) s[nf][3] = -1e30f;
                }
            }
            float mx0 = m0, mx1 = m1;
#pragma unroll
            for (int nf = 0; nf < 8; ++nf) {
                mx0 = fmaxf(mx0, fmaxf(s[nf][0], s[nf][1]));
                mx1 = fmaxf(mx1, fmaxf(s[nf][2], s[nf][3]));
            }
            mx0 = fmaxf(mx0, __shfl_xor_sync(0xffffffffu, mx0, 1));
            mx0 = fmaxf(mx0, __shfl_xor_sync(0xffffffffu, mx0, 2));
            mx1 = fmaxf(mx1, __shfl_xor_sync(0xffffffffu, mx1, 1));
            mx1 = fmaxf(mx1, __shfl_xor_sync(0xffffffffu, mx1, 2));
            const float a0 = __expf(m0 - mx0), a1 = __expf(m1 - mx1);
            m0 = mx0; m1 = mx1;
            float sum0 = 0.f, sum1 = 0.f;
#pragma unroll
            for (int nf = 0; nf < 8; ++nf) {
                s[nf][0] = __expf(s[nf][0] - mx0);
                s[nf][1] = __expf(s[nf][1] - mx0);
                s[nf][2] = __expf(s[nf][2] - mx1);
                s[nf][3] = __expf(s[nf][3] - mx1);
                sum0 += s[nf][0] + s[nf][1];
                sum1 += s[nf][2] + s[nf][3];
            }
            sum0 += __shfl_xor_sync(0xffffffffu, sum0, 1);
            sum0 += __shfl_xor_sync(0xffffffffu, sum0, 2);
            sum1 += __shfl_xor_sync(0xffffffffu, sum1, 1);
            sum1 += __shfl_xor_sync(0xffffffffu, sum1, 2);
            l0 = l0 * a0 + sum0;
            l1 = l1 * a1 + sum1;
#pragma unroll
            for (int nf = 0; nf < 16; ++nf) {
                o[nf][0] *= a0; o[nf][1] *= a0;
                o[nf][2] *= a1; o[nf][3] *= a1;
            }
#pragma unroll
            for (int ks2 = 0; ks2 < 4; ++ks2) {
                uint32_t ah[4], al[4];
                ah[0] = pack_hilo(s[2*ks2][0],   s[2*ks2][1],   al[0]);
                ah[1] = pack_hilo(s[2*ks2][2],   s[2*ks2][3],   al[1]);
                ah[2] = pack_hilo(s[2*ks2+1][0], s[2*ks2+1][1], al[2]);
                ah[3] = pack_hilo(s[2*ks2+1][2], s[2*ks2+1][3], al[3]);
#pragma unroll
                for (int dp = 0; dp < 4; ++dp) {
                    uint32_t v0h[4], v0l[4], v1h[4], v1l[4];
                    const uint32_t vb = sb + voff + ks2 * (16 * FROWB) + dp * 64;
                    ldsm_x4t(v0h, vb + FVH);
                    ldsm_x4t(v0l, vb + FVL);
                    ldsm_x4t(v1h, vb + FVH + 32);
                    ldsm_x4t(v1l, vb + FVL + 32);
                    float* o0 = o[4*dp + 0];
                    float* o1 = o[4*dp + 1];
                    float* o2 = o[4*dp + 2];
                    float* o3 = o[4*dp + 3];
                    mma_bf16(o0, ah, v0h[0], v0h[1]);
                    mma_bf16(o1, ah, v0h[2], v0h[3]);
                    mma_bf16(o2, ah, v1h[0], v1h[1]);
                    mma_bf16(o3, ah, v1h[2], v1h[3]);
                    mma_bf16(o0, ah, v0l[0], v0l[1]);
                    mma_bf16(o1, ah, v0l[2], v0l[3]);
                    mma_bf16(o2, ah, v1l[0], v1l[1]);
                    mma_bf16(o3, ah, v1l[2], v1l[3]);
                    mma_bf16(o0, al, v0h[0], v0h[1]);
                    mma_bf16(o1, al, v0h[2], v0h[3]);
                    mma_bf16(o2, al, v1h[0], v1h[1]);
                    mma_bf16(o3, al, v1h[2], v1h[3]);
                }
            }
        }
    }

    const float inv0 = 1.f / l0, inv1 = 1.f / l1;
    const int b = bh >> 4, hd = bh & 15;
    const size_t ob0 = ((size_t)(b * SEQ + r0g)) * HID + hd * HDIM;
    const size_t ob1 = ob0 + (size_t)8 * HID;
#pragma unroll
    for (int nf = 0; nf < 16; ++nf) {
        const int col = nf * 8 + (lane & 3) * 2;
        uint32_t lo;
        uint32_t hi = pack_hilo(o[nf][0] * inv0, o[nf][1] * inv0, lo);
        *(uint32_t*)(g_attn_hi + ob0 + col) = hi;
        *(uint32_t*)(g_attn_lo + ob0 + col) = lo;
        hi = pack_hilo(o[nf][2] * inv1, o[nf][3] * inv1, lo);
        *(uint32_t*)(g_attn_hi + ob1 + col) = hi;
        *(uint32_t*)(g_attn_lo + ob1 + col) = lo;
    }
}

// ---------------------------------------------------------------------------
extern "C" void kernel_launch(void* const* d_in, const int* in_sizes, int n_in,
                              void* d_out, int out_size)
{
    const float* hs    = (const float*)d_in[0];
    const float* W_in  = (const float*)d_in[1];
    const float* b_in  = (const float*)d_in[2];
    const float* W_out = (const float*)d_in[3];
    const float* b_out = (const float*)d_in[4];
    float* out = (float*)d_out;
    (void)in_sizes; (void)n_in; (void)out_size;

    cudaFuncSetAttribute(gemm_mma_kernel<0, HID>,
                         cudaFuncAttributeMaxDynamicSharedMemorySize, GEMM_SMEM);
    cudaFuncSetAttribute(gemm_mma_kernel<1, HID>,
                         cudaFuncAttributeMaxDynamicSharedMemorySize, GEMM_SMEM);
    cudaFuncSetAttribute(flash_mma_kernel,
                         cudaFuncAttributeMaxDynamicSharedMemorySize, FLASH_SMEM);

    __nv_bfloat16 *hs_hi, *hs_lo, *win_hi, *win_lo, *wout_hi, *wout_lo, *at_hi, *at_lo;
    cudaGetSymbolAddress((void**)&hs_hi,   g_hs_hi);
    cudaGetSymbolAddress((void**)&hs_lo,   g_hs_lo);
    cudaGetSymbolAddress((void**)&win_hi,  g_win_hi);
    cudaGetSymbolAddress((void**)&win_lo,  g_win_lo);
    cudaGetSymbolAddress((void**)&wout_hi, g_wout_hi);
    cudaGetSymbolAddress((void**)&wout_lo, g_wout_lo);
    cudaGetSymbolAddress((void**)&at_hi,   g_attn_hi);
    cudaGetSymbolAddress((void**)&at_lo,   g_attn_lo);

    cvt_hilo_kernel<<<2048, 256>>>(hs,    hs_hi,   hs_lo,   MROWS * HID / 4);
    cvt_hilo_kernel<<<2048, 256>>>(W_in,  win_hi,  win_lo,  NQKV * HID / 4);
    cvt_hilo_kernel<<<2048, 256>>>(W_out, wout_hi, wout_lo, HID * HID / 4);

    gemm_mma_kernel<0, HID><<<dim3(NQKV / 256, MROWS / 128), 512, GEMM_SMEM>>>(
        hs_hi, hs_lo, win_hi, win_lo, b_in, nullptr);

    flash_mma_kernel<<<dim3(SEQ / 128, BATCH * NHEADS), 256, FLASH_SMEM>>>();

    gemm_mma_kernel<1, HID><<<dim3(HID / 256, MROWS / 128), 512, GEMM_SMEM>>>(
        at_hi, at_lo, wout_hi, wout_lo, b_out, out);
}